// round 13
// baseline (speedup 1.0000x reference)
#include <cuda_runtime.h>
#include <cuda_bf16.h>
#include <math.h>
#include <stdint.h>

#define BATCH 512
#define SEQ   201
#define EMBD  128
#define NHEAD 4
#define HDIM  32
#define FFD   256
#define NEXP  5
#define NLAYER 6
#define NTOK  (BATCH*SEQ)          // 102912

typedef __nv_bfloat16 bf16;

// ---------------- scratch (device globals; no runtime allocation) ----------
__device__ float g_x   [(size_t)NTOK*EMBD];
__device__ float g_qkv [(size_t)NTOK*3*EMBD];
__device__ float g_gate[(size_t)NTOK*NEXP];
__device__ bf16  g_hh  [(size_t)NTOK*EMBD];
__device__ bf16  g_hl  [(size_t)NTOK*EMBD];
__device__ bf16  g_oh  [(size_t)NTOK*EMBD];
__device__ bf16  g_ol  [(size_t)NTOK*EMBD];
__device__ bf16  g_hidh[(size_t)NTOK*NEXP*FFD];
__device__ bf16  g_hidl[(size_t)NTOK*NEXP*FFD];
// weight planes
__device__ bf16  g_wqkvh[(size_t)NLAYER*3*EMBD*EMBD], g_wqkvl[(size_t)NLAYER*3*EMBD*EMBD];
__device__ bf16  g_woh  [(size_t)NLAYER*EMBD*EMBD],   g_wol  [(size_t)NLAYER*EMBD*EMBD];
__device__ bf16  g_w1h  [(size_t)NLAYER*NEXP*FFD*EMBD], g_w1l[(size_t)NLAYER*NEXP*FFD*EMBD];
__device__ bf16  g_w2h  [(size_t)NLAYER*EMBD*NEXP*FFD], g_w2l[(size_t)NLAYER*EMBD*NEXP*FFD];

// ---------------- helpers -----------------------------------------------------
__device__ __forceinline__ void split2(float x, float y, uint32_t& hi, uint32_t& lo) {
    __nv_bfloat162 h, l;
    h.x = __float2bfloat16(x); h.y = __float2bfloat16(y);
    l.x = __float2bfloat16(x - __bfloat162float(h.x));
    l.y = __float2bfloat16(y - __bfloat162float(h.y));
    hi = *(uint32_t*)&h; lo = *(uint32_t*)&l;
}

#define MMA_BF16(d, a, b0, b1)                                                   \
    asm volatile("mma.sync.aligned.m16n8k16.row.col.f32.bf16.bf16.f32 "          \
                 "{%0,%1,%2,%3},{%4,%5,%6,%7},{%8,%9},{%0,%1,%2,%3};"            \
                 : "+f"(d[0]), "+f"(d[1]), "+f"(d[2]), "+f"(d[3])                 \
                 : "r"(a[0]), "r"(a[1]), "r"(a[2]), "r"(a[3]), "r"(b0), "r"(b1))

#define CP_ASYNC16(saddr, gaddr)                                                  \
    asm volatile("cp.async.cg.shared.global [%0], [%1], 16;" :: "r"(saddr), "l"(gaddr))

#define LDSM_X4(r0, r1, r2, r3, addr)                                             \
    asm volatile("ldmatrix.sync.aligned.m8n8.x4.shared.b16 {%0,%1,%2,%3}, [%4];"  \
                 : "=r"(r0), "=r"(r1), "=r"(r2), "=r"(r3) : "r"(addr))

#define LDSM_X2(r0, r1, addr)                                                     \
    asm volatile("ldmatrix.sync.aligned.m8n8.x2.shared.b16 {%0,%1}, [%2];"        \
                 : "=r"(r0), "=r"(r1) : "r"(addr))

// ---------------- fused embed+LN0 / weight-split prep -------------------------
#define WSPLIT_N  (NLAYER*4*EMBD*EMBD)          // 393216 = 3072*128
#define PREP_GRID (NTOK + WSPLIT_N/128)

__global__ void prep_kernel(const int* __restrict__ x_cat,
                            const float* __restrict__ x_num,
                            const float* __restrict__ x_eng,
                            const float* __restrict__ emb,
                            const float* __restrict__ emb_bias,
                            const float* __restrict__ emb_eng,
                            const float* __restrict__ emb_bias_eng,
                            const float* __restrict__ w,
                            const float* __restrict__ bb,
                            float* __restrict__ xout,
                            const float* __restrict__ Wqkv,
                            bf16* __restrict__ wqh, bf16* __restrict__ wql,
                            const float* __restrict__ Wo,
                            bf16* __restrict__ woh, bf16* __restrict__ wol)
{
    if (blockIdx.x >= NTOK) {
        int i = (blockIdx.x - NTOK)*128 + threadIdx.x;
        const int na = NLAYER*3*EMBD*EMBD;
        if (i < na) {
            float v = Wqkv[i];
            bf16 h = __float2bfloat16(v);
            wqh[i] = h;
            wql[i] = __float2bfloat16(v - __bfloat162float(h));
        } else {
            int j = i - na;
            float v = Wo[j];
            bf16 h = __float2bfloat16(v);
            woh[j] = h;
            wol[j] = __float2bfloat16(v - __bfloat162float(h));
        }
        return;
    }

    int tok = blockIdx.x;
    int b = tok / SEQ, t = tok % SEQ;
    int j = threadIdx.x;

    float v;
    if (t < 53) {
        int idx = x_cat[(b*51 + 50)*53 + t];
        v = emb[(size_t)idx*EMBD + j] + emb_bias[t*EMBD + j];
    } else if (t < 100) {
        int c = t - 53;
        v = emb[(size_t)(1306 + c)*EMBD + j] * x_num[(b*51 + 50)*47 + c]
            + emb_bias[t*EMBD + j];
    } else if (t < 200) {
        int c = t - 100;
        v = emb_eng[c*EMBD + j] * x_eng[b*100 + c] + emb_bias_eng[c*EMBD + j];
    } else {
        v = 0.f;
    }

    __shared__ float red[8];
    int lane = j & 31, warp = j >> 5;
    float s = v;
    #pragma unroll
    for (int o = 16; o; o >>= 1) s += __shfl_xor_sync(0xffffffffu, s, o);
    if (lane == 0) red[warp] = s;
    __syncthreads();
    float m = (red[0] + red[1] + red[2] + red[3]) * (1.f/128.f);
    float d = v - m;
    float s2 = d * d;
    #pragma unroll
    for (int o = 16; o; o >>= 1) s2 += __shfl_xor_sync(0xffffffffu, s2, o);
    if (lane == 0) red[4 + warp] = s2;
    __syncthreads();
    float var = (red[4] + red[5] + red[6] + red[7]) * (1.f/128.f);
    xout[(size_t)tok*EMBD + j] = d * rsqrtf(var + 1e-5f) * w[j] + bb[j];
}

__global__ void trans_split(const float* __restrict__ in, bf16* __restrict__ oh,
                            bf16* __restrict__ ol, int R, int C)
{
    __shared__ float tile[32][33];
    int mat = blockIdx.z;
    const float* src = in + (size_t)mat*R*C;
    int c0 = blockIdx.x*32, r0 = blockIdx.y*32;
    int x = threadIdx.x, y = threadIdx.y;
    #pragma unroll
    for (int i = 0; i < 32; i += 8)
        tile[y+i][x] = src[(size_t)(r0+y+i)*C + c0+x];
    __syncthreads();
    #pragma unroll
    for (int i = 0; i < 32; i += 8) {
        float v = tile[x][y+i];
        size_t idx = (size_t)mat*R*C + (size_t)(c0+y+i)*R + r0+x;
        bf16 h = __float2bfloat16(v);
        oh[idx] = h;
        ol[idx] = __float2bfloat16(v - __bfloat162float(h));
    }
}

// ---------------- warp-per-token LayerNorm -> bf16 hi/lo planes ---------------
__global__ void ln_warp_p(const float* __restrict__ src,
                          bf16* __restrict__ dh, bf16* __restrict__ dl,
                          const float* __restrict__ w, const float* __restrict__ bb,
                          int t0, int tstride)
{
    int lane = threadIdx.x & 31;
    int tokl = blockIdx.x * (blockDim.x >> 5) + (threadIdx.x >> 5);
    size_t tok = (size_t)t0 + (size_t)tokl * tstride;

    float4 v = *(const float4*)(src + tok*EMBD + lane*4);
    float s = v.x + v.y + v.z + v.w;
    #pragma unroll
    for (int o = 16; o; o >>= 1) s += __shfl_xor_sync(0xffffffffu, s, o);
    float m = s * (1.f/128.f);
    float dx = v.x-m, dy = v.y-m, dz = v.z-m, dw = v.w-m;
    float s2 = dx*dx + dy*dy + dz*dz + dw*dw;
    #pragma unroll
    for (int o = 16; o; o >>= 1) s2 += __shfl_xor_sync(0xffffffffu, s2, o);
    float inv = rsqrtf(s2 * (1.f/128.f) + 1e-5f);
    float4 wv = *(const float4*)(w + lane*4);
    float4 bv = *(const float4*)(bb + lane*4);
    float r0 = dx*inv*wv.x + bv.x, r1 = dy*inv*wv.y + bv.y;
    float r2 = dz*inv*wv.z + bv.z, r3 = dw*inv*wv.w + bv.w;
    uint32_t h0,l0,h1,l1;
    split2(r0, r1, h0, l0); split2(r2, r3, h1, l1);
    uint32_t* ph = (uint32_t*)(dh + tok*EMBD + lane*4);
    uint32_t* pl = (uint32_t*)(dl + tok*EMBD + lane*4);
    ph[0] = h0; ph[1] = h1; pl[0] = l0; pl[1] = l1;
}

// ---------------- fused LN2 + gate softmax -> planes --------------------------
__global__ void ln2g_p(const float* __restrict__ src,
                       bf16* __restrict__ dh, bf16* __restrict__ dl,
                       const float* __restrict__ w, const float* __restrict__ bb,
                       const float* __restrict__ Wg, const float* __restrict__ bg,
                       float* __restrict__ gate, int t0, int tstride)
{
    int lane = threadIdx.x & 31;
    int tokl = blockIdx.x * (blockDim.x >> 5) + (threadIdx.x >> 5);
    size_t tok = (size_t)t0 + (size_t)tokl * tstride;

    float4 v = *(const float4*)(src + tok*EMBD + lane*4);
    float s = v.x + v.y + v.z + v.w;
    #pragma unroll
    for (int o = 16; o; o >>= 1) s += __shfl_xor_sync(0xffffffffu, s, o);
    float m = s * (1.f/128.f);
    float dx = v.x-m, dy = v.y-m, dz = v.z-m, dw = v.w-m;
    float s2 = dx*dx + dy*dy + dz*dz + dw*dw;
    #pragma unroll
    for (int o = 16; o; o >>= 1) s2 += __shfl_xor_sync(0xffffffffu, s2, o);
    float inv = rsqrtf(s2 * (1.f/128.f) + 1e-5f);
    float4 wv = *(const float4*)(w + lane*4);
    float4 bv = *(const float4*)(bb + lane*4);
    float h[4];
    h[0] = dx*inv*wv.x + bv.x; h[1] = dy*inv*wv.y + bv.y;
    h[2] = dz*inv*wv.z + bv.z; h[3] = dw*inv*wv.w + bv.w;
    uint32_t hh0,ll0,hh1,ll1;
    split2(h[0], h[1], hh0, ll0); split2(h[2], h[3], hh1, ll1);
    uint32_t* ph = (uint32_t*)(dh + tok*EMBD + lane*4);
    uint32_t* pl = (uint32_t*)(dl + tok*EMBD + lane*4);
    ph[0] = hh0; ph[1] = hh1; pl[0] = ll0; pl[1] = ll1;

    float p[NEXP];
    #pragma unroll
    for (int e = 0; e < NEXP; e++) p[e] = 0.f;
    #pragma unroll
    for (int q = 0; q < 4; q++) {
        int j = lane*4 + q;
        #pragma unroll
        for (int e = 0; e < NEXP; e++) p[e] += h[q] * Wg[j*NEXP + e];
    }
    #pragma unroll
    for (int e = 0; e < NEXP; e++)
        #pragma unroll
        for (int o = 16; o; o >>= 1) p[e] += __shfl_xor_sync(0xffffffffu, p[e], o);
    if (lane == 0) {
        float mx = -1e30f;
        #pragma unroll
        for (int e = 0; e < NEXP; e++) { p[e] += bg[e]; mx = fmaxf(mx, p[e]); }
        float sum = 0.f;
        #pragma unroll
        for (int e = 0; e < NEXP; e++) { p[e] = __expf(p[e] - mx); sum += p[e]; }
        float is = 1.f / sum;
        #pragma unroll
        for (int e = 0; e < NEXP; e++) gate[tok*NEXP + e] = p[e] * is;
    }
}

// ---------------- bf16x3 GEMM: ldmatrix + 3-stage cp.async --------------------
// Stage is issued BEFORE compute each iteration (post-sync WAR-safe).
#define GEMM_KP   24
#define GEMM_PL   (128*GEMM_KP)
#define GEMM_SMEM (4*3*GEMM_PL*2)   // 73728 bytes

template<int EPI>
__global__ void __launch_bounds__(256, 2)
gemm_p(const bf16* __restrict__ Ahp, const bf16* __restrict__ Alp, long rsA,
       const bf16* __restrict__ Bhp, const bf16* __restrict__ Blp,
       const float* __restrict__ bias,
       float* __restrict__ C, long rsC,
       bf16* __restrict__ Chp, bf16* __restrict__ Clp,
       const float* __restrict__ gate, long rsG,
       int K)
{
    constexpr int KP = GEMM_KP;
    constexpr int PL = GEMM_PL;
    extern __shared__ bf16 smg[];
    bf16* Ah = smg;
    bf16* Al = Ah + 3*PL;
    bf16* Bh = Al + 3*PL;
    bf16* Bl = Bh + 3*PL;

    const int tid  = threadIdx.x;
    const int warp = tid >> 5, lane = tid & 31;
    const int g = lane >> 2, r = lane & 3;
    const int wm = (warp & 3) * 32;
    const int wn = (warp >> 2) * 64;
    const int bx = blockIdx.x, by = blockIdx.y;

    float c[2][8][4];
    #pragma unroll
    for (int mi = 0; mi < 2; mi++)
        #pragma unroll
        for (int ni = 0; ni < 8; ni++)
            #pragma unroll
            for (int q = 0; q < 4; q++) c[mi][ni][q] = 0.f;

    const int crow = tid >> 1;
    const int ckseg = (tid & 1) << 3;
    const bf16* gAh = Ahp + (size_t)(by*128 + crow)*rsA + ckseg;
    const bf16* gAl = Alp + (size_t)(by*128 + crow)*rsA + ckseg;
    const bf16* gBh = Bhp + (size_t)(bx*128 + crow)*K + ckseg;
    const bf16* gBl = Blp + (size_t)(bx*128 + crow)*K + ckseg;

    uint32_t baseAh = (uint32_t)__cvta_generic_to_shared(Ah);
    uint32_t baseAl = (uint32_t)__cvta_generic_to_shared(Al);
    uint32_t baseBh = (uint32_t)__cvta_generic_to_shared(Bh);
    uint32_t baseBl = (uint32_t)__cvta_generic_to_shared(Bl);

    auto stage = [&](int k0, int s) {
        uint32_t off = (uint32_t)(s*PL + crow*KP + ckseg) * 2;
        CP_ASYNC16(baseAh + off, gAh + k0);
        CP_ASYNC16(baseAl + off, gAl + k0);
        CP_ASYNC16(baseBh + off, gBh + k0);
        CP_ASYNC16(baseBl + off, gBl + k0);
        asm volatile("cp.async.commit_group;" ::: "memory");
    };

    uint32_t a_off[2];
    #pragma unroll
    for (int mi = 0; mi < 2; mi++)
        a_off[mi] = (uint32_t)(((wm + mi*16 + (lane & 15))*KP + ((lane >> 4) << 3)) * 2);
    uint32_t b_off[4];
    #pragma unroll
    for (int p = 0; p < 4; p++)
        b_off[p] = (uint32_t)(((wn + p*16 + (lane & 7) + ((lane >> 4) << 3))*KP
                               + (((lane >> 3) & 1) << 3)) * 2);

    auto compute = [&](int s) {
        uint32_t so = (uint32_t)(s*PL*2);
        uint32_t ah[2][4], al[2][4];
        #pragma unroll
        for (int mi = 0; mi < 2; mi++) {
            LDSM_X4(ah[mi][0], ah[mi][1], ah[mi][2], ah[mi][3], baseAh + so + a_off[mi]);
            LDSM_X4(al[mi][0], al[mi][1], al[mi][2], al[mi][3], baseAl + so + a_off[mi]);
        }
        #pragma unroll
        for (int p = 0; p < 4; p++) {
            uint32_t bh[4], bl[4];
            LDSM_X4(bh[0], bh[1], bh[2], bh[3], baseBh + so + b_off[p]);
            LDSM_X4(bl[0], bl[1], bl[2], bl[3], baseBl + so + b_off[p]);
            MMA_BF16(c[0][2*p],   ah[0], bh[0], bh[1]);
            MMA_BF16(c[1][2*p],   ah[1], bh[0], bh[1]);
            MMA_BF16(c[0][2*p+1], ah[0], bh[2], bh[3]);
            MMA_BF16(c[1][2*p+1], ah[1], bh[2], bh[3]);
            MMA_BF16(c[0][2*p],   al[0], bh[0], bh[1]);
            MMA_BF16(c[1][2*p],   al[1], bh[0], bh[1]);
            MMA_BF16(c[0][2*p+1], al[0], bh[2], bh[3]);
            MMA_BF16(c[1][2*p+1], al[1], bh[2], bh[3]);
            MMA_BF16(c[0][2*p],   ah[0], bl[0], bl[1]);
            MMA_BF16(c[1][2*p],   ah[1], bl[0], bl[1]);
            MMA_BF16(c[0][2*p+1], ah[0], bl[2], bl[3]);
            MMA_BF16(c[1][2*p+1], ah[1], bl[2], bl[3]);
        }
    };

    const int nk = K >> 4;
    stage(0, 0);
    if (nk > 1) stage(16, 1);
    for (int it = 0; it < nk; ++it) {
        if (it + 1 < nk) asm volatile("cp.async.wait_group 1;" ::: "memory");
        else             asm volatile("cp.async.wait_group 0;" ::: "memory");
        __syncthreads();
        if (it + 2 < nk) stage((it + 2) << 4, (it + 2) % 3);   // before compute
        compute(it % 3);
    }

    // ---------------- epilogue ----------------
    if (EPI == 4) {
        #pragma unroll
        for (int mi = 0; mi < 2; mi++)
            #pragma unroll
            for (int half = 0; half < 2; half++) {
                int m = by*128 + wm + mi*16 + g + half*8;
                float gg[NEXP];
                #pragma unroll
                for (int e = 0; e < NEXP; e++) gg[e] = gate[(size_t)m*rsG + e];
                float* crow2 = C + (size_t)m*rsC;
                #pragma unroll
                for (int ni = 0; ni < 8; ni++) {
                    int col = wn + ni*8 + 2*r;
                    float a0 = 0.f, a1 = 0.f;
                    #pragma unroll
                    for (int e = 0; e < NEXP; e++) {
                        a0 += gg[e] * bias[e*128 + col];
                        a1 += gg[e] * bias[e*128 + col + 1];
                    }
                    float2 old = *(float2*)(crow2 + col);
                    old.x += c[mi][ni][half*2 + 0] + a0;
                    old.y += c[mi][ni][half*2 + 1] + a1;
                    *(float2*)(crow2 + col) = old;
                }
            }
    } else if (EPI == 1) {
        #pragma unroll
        for (int mi = 0; mi < 2; mi++)
            #pragma unroll
            for (int half = 0; half < 2; half++) {
                int m = by*128 + wm + mi*16 + g + half*8;
                float gv = gate[(size_t)m*rsG + (bx >> 1)];
                #pragma unroll
                for (int ni = 0; ni < 8; ni++) {
                    int n = wn + ni*8 + 2*r;
                    float v0 = fmaxf(c[mi][ni][half*2+0] + bias[bx*128 + n],   0.f) * gv;
                    float v1 = fmaxf(c[mi][ni][half*2+1] + bias[bx*128 + n+1], 0.f) * gv;
                    uint32_t hi, lo;
                    split2(v0, v1, hi, lo);
                    *(uint32_t*)(Chp + (size_t)m*rsC + bx*128 + n) = hi;
                    *(uint32_t*)(Clp + (size_t)m*rsC + bx*128 + n) = lo;
                }
            }
    } else {
        #pragma unroll
        for (int mi = 0; mi < 2; mi++)
            #pragma unroll
            for (int half = 0; half < 2; half++) {
                int m = by*128 + wm + mi*16 + g + half*8;
                float* crow2 = C + (size_t)m*rsC + bx*128;
                const float* brow = bias + bx*128;
                #pragma unroll
                for (int ni = 0; ni < 8; ni++) {
                    int n = wn + ni*8 + 2*r;
                    float v0 = c[mi][ni][half*2 + 0] + brow[n];
                    float v1 = c[mi][ni][half*2 + 1] + brow[n+1];
                    if (EPI == 0) {
                        *(float2*)(crow2 + n) = make_float2(v0, v1);
                    } else {
                        float2 old = *(float2*)(crow2 + n);
                        old.x += v0; old.y += v1;
                        *(float2*)(crow2 + n) = old;
                    }
                }
            }
    }
}

// ---------------- streaming mma attention (P in registers, 3 CTAs/SM) ---------
#define KSTR 40
#define VSTR 216
#define ATTN_SMEM ((208*KSTR + 32*VSTR)*2*2)   // 60928 bytes

__global__ void __launch_bounds__(256, 3)
attn_mma(const float* __restrict__ qkv, bf16* __restrict__ ohi, bf16* __restrict__ olo,
         int qt0)
{
    extern __shared__ char smraw[];
    bf16* Kh = (bf16*)smraw;                 // [208][KSTR]   ([key][d])
    bf16* Kl = Kh + 208*KSTR;
    bf16* Vh = Kl + 208*KSTR;                // [32][VSTR]    ([d][key])
    bf16* Vl = Vh + 32*VSTR;

    const int bh0_ = blockIdx.x, b = bh0_ >> 2, h = bh0_ & 3;
    const float* base = qkv + (size_t)b*SEQ*(3*EMBD) + h*HDIM;
    const int tid = threadIdx.x, warp = tid >> 5, lane = tid & 31;
    const int g = lane >> 2, r = lane & 3;
    const float scale = 0.1767766952966369f;   // 1/sqrt(32)

    uint32_t baseKh = (uint32_t)__cvta_generic_to_shared(Kh);
    uint32_t baseKl = (uint32_t)__cvta_generic_to_shared(Kl);
    uint32_t baseVh = (uint32_t)__cvta_generic_to_shared(Vh);
    uint32_t baseVl = (uint32_t)__cvta_generic_to_shared(Vl);

    for (int idx = tid; idx < 208*32; idx += 256) {
        int t = idx >> 5, d = idx & 31;
        float kv = 0.f, vv = 0.f;
        if (t < SEQ) {
            kv = base[(size_t)t*(3*EMBD) + EMBD   + d];
            vv = base[(size_t)t*(3*EMBD) + 2*EMBD + d];
        }
        bf16 khv = __float2bfloat16(kv);
        Kh[t*KSTR + d] = khv;
        Kl[t*KSTR + d] = __float2bfloat16(kv - __bfloat162float(khv));
        bf16 vhv = __float2bfloat16(vv);
        Vh[d*VSTR + t] = vhv;
        Vl[d*VSTR + t] = __float2bfloat16(vv - __bfloat162float(vhv));
    }
    __syncthreads();

    const uint32_t kofl = (uint32_t)((((lane & 7))*KSTR + (((lane >> 3) & 3) << 3)) * 2);
    const uint32_t vofl = (uint32_t)((((lane & 7))*VSTR + (((lane >> 3) & 1) << 3)) * 2);

    for (int t = qt0 + warp; t < 13; t += 8) {
        const int qbase = t*16;

        uint32_t qh[2][4], ql[2][4];
        #pragma unroll
        for (int ks = 0; ks < 2; ks++)
            #pragma unroll
            for (int j = 0; j < 4; j++) {
                int qq = qbase + g + ((j & 1) << 3);
                if (qq > 200) qq = 200;
                int kk = ks*16 + 2*r + ((j >> 1) << 3);
                float2 v = *(const float2*)(base + (size_t)qq*(3*EMBD) + kk);
                split2(v.x*scale, v.y*scale, qh[ks][j], ql[ks][j]);
            }

        float oc[4][4];
        #pragma unroll
        for (int ni = 0; ni < 4; ni++)
            #pragma unroll
            for (int q = 0; q < 4; q++) oc[ni][q] = 0.f;
        float osum0 = 0.f, osum1 = 0.f;

        for (int kt = 0; kt < 13; kt++) {
            float s[2][4];
            #pragma unroll
            for (int p = 0; p < 2; p++) {
                s[p][0] = s[p][1] = s[p][2] = s[p][3] = 0.f;
                uint32_t ko = (uint32_t)((kt*16 + p*8)*KSTR*2) + kofl;
                uint32_t kb[4], klv[4];
                LDSM_X4(kb[0], kb[1], kb[2], kb[3], baseKh + ko);
                LDSM_X4(klv[0], klv[1], klv[2], klv[3], baseKl + ko);
                MMA_BF16(s[p], qh[0], kb[0], kb[1]);
                MMA_BF16(s[p], ql[0], kb[0], kb[1]);
                MMA_BF16(s[p], qh[0], klv[0], klv[1]);
                MMA_BF16(s[p], qh[1], kb[2], kb[3]);
                MMA_BF16(s[p], ql[1], kb[2], kb[3]);
                MMA_BF16(s[p], qh[1], klv[2], klv[3]);
            }
            #pragma unroll
            for (int p = 0; p < 2; p++) {
                int c0 = kt*16 + p*8 + 2*r;
                float e0 = (c0     <= 200) ? __expf(s[p][0]) : 0.f;
                float e1 = (c0 + 1 <= 200) ? __expf(s[p][1]) : 0.f;
                float e2 = (c0     <= 200) ? __expf(s[p][2]) : 0.f;
                float e3 = (c0 + 1 <= 200) ? __expf(s[p][3]) : 0.f;
                s[p][0] = e0; s[p][1] = e1; s[p][2] = e2; s[p][3] = e3;
                osum0 += e0 + e1;
                osum1 += e2 + e3;
            }
            uint32_t pah[4], pal[4];
            split2(s[0][0], s[0][1], pah[0], pal[0]);
            split2(s[0][2], s[0][3], pah[1], pal[1]);
            split2(s[1][0], s[1][1], pah[2], pal[2]);
            split2(s[1][2], s[1][3], pah[3], pal[3]);
            #pragma unroll
            for (int ni = 0; ni < 4; ni++) {
                uint32_t vo = (uint32_t)((ni*8*VSTR + kt*16)*2) + vofl;
                uint32_t vh0, vh1, vl0, vl1;
                LDSM_X2(vh0, vh1, baseVh + vo);
                LDSM_X2(vl0, vl1, baseVl + vo);
                MMA_BF16(oc[ni], pah, vh0, vh1);
                MMA_BF16(oc[ni], pal, vh0, vh1);
                MMA_BF16(oc[ni], pah, vl0, vl1);
            }
        }

        osum0 += __shfl_xor_sync(0xffffffffu, osum0, 1);
        osum0 += __shfl_xor_sync(0xffffffffu, osum0, 2);
        osum1 += __shfl_xor_sync(0xffffffffu, osum1, 1);
        osum1 += __shfl_xor_sync(0xffffffffu, osum1, 2);
        float inv0 = 1.f / osum0, inv1 = 1.f / osum1;

        int q0r = qbase + g, q1r = qbase + g + 8;
        #pragma unroll
        for (int ni = 0; ni < 4; ni++) {
            int d = ni*8 + 2*r;
            if (q0r <= 200) {
                uint32_t hi, lo;
                split2(oc[ni][0]*inv0, oc[ni][1]*inv0, hi, lo);
                size_t off = ((size_t)b*SEQ + q0r)*EMBD + h*HDIM + d;
                *(uint32_t*)(ohi + off) = hi;
                *(uint32_t*)(olo + off) = lo;
            }
            if (q1r <= 200) {
                uint32_t hi, lo;
                split2(oc[ni][2]*inv1, oc[ni][3]*inv1, hi, lo);
                size_t off = ((size_t)b*SEQ + q1r)*EMBD + h*HDIM + d;
                *(uint32_t*)(ohi + off) = hi;
                *(uint32_t*)(olo + off) = lo;
            }
        }
    }
}

// ---------------- output copy -------------------------------------------------
__global__ void copy_out_kernel(const float* __restrict__ x, float* __restrict__ out)
{
    int b = blockIdx.x, j = threadIdx.x;
    out[b*EMBD + j] = x[((size_t)b*SEQ + 200)*EMBD + j];
}

// ---------------- launcher ----------------------------------------------------
extern "C" void kernel_launch(void* const* d_in, const int* in_sizes, int n_in,
                              void* d_out, int out_size)
{
    (void)in_sizes; (void)n_in; (void)out_size;

    const int*   x_cat        = (const int*)  d_in[0];
    const float* x_num        = (const float*)d_in[1];
    const float* x_eng        = (const float*)d_in[2];
    const float* emb          = (const float*)d_in[3];
    const float* emb_bias     = (const float*)d_in[4];
    const float* emb_eng      = (const float*)d_in[5];
    const float* emb_bias_eng = (const float*)d_in[6];
    const float* ln0_w        = (const float*)d_in[7];
    const float* ln0_b        = (const float*)d_in[8];
    const float* ln1_w        = (const float*)d_in[9];
    const float* ln1_b        = (const float*)d_in[10];
    const float* Wqkv         = (const float*)d_in[11];
    const float* bqkv         = (const float*)d_in[12];
    const float* Wo           = (const float*)d_in[13];
    const float* bo           = (const float*)d_in[14];
    const float* ln2_w        = (const float*)d_in[15];
    const float* ln2_b        = (const float*)d_in[16];
    const float* Wg           = (const float*)d_in[17];
    const float* bg           = (const float*)d_in[18];
    const float* W1           = (const float*)d_in[19];
    const float* b1           = (const float*)d_in[20];
    const float* W2           = (const float*)d_in[21];
    const float* b2           = (const float*)d_in[22];
    float* out = (float*)d_out;

    float *px, *pqkv, *pgate;
    bf16 *phh, *phl, *poh, *pol, *phidh, *phidl;
    bf16 *pwqkvh, *pwqkvl, *pwoh, *pwol, *pw1h, *pw1l, *pw2h, *pw2l;
    cudaGetSymbolAddress((void**)&px,    g_x);
    cudaGetSymbolAddress((void**)&pqkv,  g_qkv);
    cudaGetSymbolAddress((void**)&pgate, g_gate);
    cudaGetSymbolAddress((void**)&phh,   g_hh);
    cudaGetSymbolAddress((void**)&phl,   g_hl);
    cudaGetSymbolAddress((void**)&poh,   g_oh);
    cudaGetSymbolAddress((void**)&pol,   g_ol);
    cudaGetSymbolAddress((void**)&phidh, g_hidh);
    cudaGetSymbolAddress((void**)&phidl, g_hidl);
    cudaGetSymbolAddress((void**)&pwqkvh, g_wqkvh);
    cudaGetSymbolAddress((void**)&pwqkvl, g_wqkvl);
    cudaGetSymbolAddress((void**)&pwoh,   g_woh);
    cudaGetSymbolAddress((void**)&pwol,   g_wol);
    cudaGetSymbolAddress((void**)&pw1h,   g_w1h);
    cudaGetSymbolAddress((void**)&pw1l,   g_w1l);
    cudaGetSymbolAddress((void**)&pw2h,   g_w2h);
    cudaGetSymbolAddress((void**)&pw2l,   g_w2l);

    cudaFuncSetAttribute(attn_mma, cudaFuncAttributeMaxDynamicSharedMemorySize, ATTN_SMEM);
    cudaFuncSetAttribute(gemm_p<0>, cudaFuncAttributeMaxDynamicSharedMemorySize, GEMM_SMEM);
    cudaFuncSetAttribute(gemm_p<1>, cudaFuncAttributeMaxDynamicSharedMemorySize, GEMM_SMEM);
    cudaFuncSetAttribute(gemm_p<3>, cudaFuncAttributeMaxDynamicSharedMemorySize, GEMM_SMEM);
    cudaFuncSetAttribute(gemm_p<4>, cudaFuncAttributeMaxDynamicSharedMemorySize, GEMM_SMEM);

    // launch order: #4 (ncu capture slot) = layer-0 attention
    prep_kernel<<<PREP_GRID, 128>>>(x_cat, x_num, x_eng, emb, emb_bias,
                                    emb_eng, emb_bias_eng, ln0_w, ln0_b, px,
                                    Wqkv, pwqkvh, pwqkvl, Wo, pwoh, pwol);       // 1
    ln_warp_p<<<NTOK/8, 256>>>(px, phh, phl, ln1_w, ln1_b, 0, 1);                // 2
    gemm_p<0><<<dim3(3, NTOK/128), 256, GEMM_SMEM>>>(phh, phl, EMBD,
                                              pwqkvh, pwqkvl, bqkv,
                                              pqkv, 3*EMBD, nullptr, nullptr,
                                              nullptr, 0, EMBD);                 // 3
    attn_mma<<<BATCH*NHEAD, 256, ATTN_SMEM>>>(pqkv, poh, pol, 0);                // 4 (profiled)
    trans_split<<<dim3(FFD/32, EMBD/32, NLAYER*NEXP), dim3(32,8)>>>(W1, pw1h, pw1l, EMBD, FFD);
    trans_split<<<dim3(EMBD/32, (NEXP*FFD)/32, NLAYER), dim3(32,8)>>>(W2, pw2h, pw2l, NEXP*FFD, EMBD);

    for (int i = 0; i < NLAYER; i++) {
        const bf16* wqh = pwqkvh + (size_t)i*3*EMBD*EMBD;
        const bf16* wql = pwqkvl + (size_t)i*3*EMBD*EMBD;
        const float* bqkv_i = bqkv + (size_t)i*3*EMBD;
        const bf16* woh = pwoh + (size_t)i*EMBD*EMBD;
        const bf16* wol = pwol + (size_t)i*EMBD*EMBD;
        const float* bo_i = bo + (size_t)i*EMBD;
        const float* wg_i = Wg + (size_t)i*EMBD*NEXP;
        const float* bg_i = bg + (size_t)i*NEXP;
        const bf16* w1h = pw1h + (size_t)i*NEXP*FFD*EMBD;
        const bf16* w1l = pw1l + (size_t)i*NEXP*FFD*EMBD;
        const float* b1_i = b1 + (size_t)i*NEXP*FFD;
        const bf16* w2h = pw2h + (size_t)i*EMBD*NEXP*FFD;
        const bf16* w2l = pw2l + (size_t)i*EMBD*NEXP*FFD;
        const float* b2_i = b2 + (size_t)i*NEXP*EMBD;

        if (i > 0) {
            ln_warp_p<<<NTOK/8, 256>>>(px, phh, phl, ln1_w + i*EMBD, ln1_b + i*EMBD, 0, 1);
            gemm_p<0><<<dim3(3, NTOK/128), 256, GEMM_SMEM>>>(phh, phl, EMBD, wqh, wql, bqkv_i,
                                                  pqkv, 3*EMBD, nullptr, nullptr,
                                                  nullptr, 0, EMBD);
            int qt0 = (i == NLAYER-1) ? 12 : 0;
            attn_mma<<<BATCH*NHEAD, 256, ATTN_SMEM>>>(pqkv, poh, pol, qt0);
        }

        if (i < NLAYER-1) {
            gemm_p<3><<<dim3(1, NTOK/128), 256, GEMM_SMEM>>>(poh, pol, EMBD, woh, wol, bo_i,
                                                  px, EMBD, nullptr, nullptr,
                                                  nullptr, 0, EMBD);
            ln2g_p<<<NTOK/8, 256>>>(px, phh, phl, ln2_w + i*EMBD, ln2_b + i*EMBD,
                                    wg_i, bg_i, pgate, 0, 1);
            gemm_p<1><<<dim3(10, NTOK/128), 256, GEMM_SMEM>>>(phh, phl, EMBD, w1h, w1l, b1_i,
                                                   nullptr, NEXP*FFD, phidh, phidl,
                                                   pgate, NEXP, EMBD);
            gemm_p<4><<<dim3(1, NTOK/128), 256, GEMM_SMEM>>>(phidh, phidl, NEXP*FFD, w2h, w2l, b2_i,
                                                  px, EMBD, nullptr, nullptr,
                                                  pgate, NEXP, NEXP*FFD);
        } else {
            const long rs = (long)SEQ*EMBD;
            gemm_p<3><<<dim3(1, BATCH/128), 256, GEMM_SMEM>>>(poh + (size_t)200*EMBD, pol + (size_t)200*EMBD, rs,
                                                   woh, wol, bo_i,
                                                   px + (size_t)200*EMBD, rs, nullptr, nullptr,
                                                   nullptr, 0, EMBD);
            ln2g_p<<<BATCH/8, 256>>>(px, phh, phl, ln2_w + i*EMBD, ln2_b + i*EMBD,
                                     wg_i, bg_i, pgate, 200, SEQ);
            gemm_p<1><<<dim3(10, BATCH/128), 256, GEMM_SMEM>>>(phh + (size_t)200*EMBD, phl + (size_t)200*EMBD, rs,
                                                    w1h, w1l, b1_i,
                                                    nullptr, NEXP*FFD, phidh, phidl,
                                                    pgate + (size_t)200*NEXP, (long)SEQ*NEXP, EMBD);
            gemm_p<4><<<dim3(1, BATCH/128), 256, GEMM_SMEM>>>(phidh, phidl, NEXP*FFD, w2h, w2l, b2_i,
                                                   px + (size_t)200*EMBD, rs, nullptr, nullptr,
                                                   pgate + (size_t)200*NEXP, (long)SEQ*NEXP,
                                                   NEXP*FFD);
        }
    }

    copy_out_kernel<<<BATCH, 128>>>(px, out);
}

// round 14
// speedup vs baseline: 1.0416x; 1.0416x over previous
#include <cuda_runtime.h>
#include <cuda_bf16.h>
#include <math.h>
#include <stdint.h>

#define BATCH 512
#define SEQ   201
#define EMBD  128
#define NHEAD 4
#define HDIM  32
#define FFD   256
#define NEXP  5
#define NLAYER 6
#define NTOK  (BATCH*SEQ)          // 102912

typedef __nv_bfloat16 bf16;

// ---------------- scratch (device globals; no runtime allocation) ----------
__device__ float g_x   [(size_t)NTOK*EMBD];
__device__ float g_qkv [(size_t)NTOK*3*EMBD];
__device__ float g_gate[(size_t)NTOK*NEXP];
__device__ bf16  g_hh  [(size_t)NTOK*EMBD];
__device__ bf16  g_hl  [(size_t)NTOK*EMBD];
__device__ bf16  g_oh  [(size_t)NTOK*EMBD];
__device__ bf16  g_ol  [(size_t)NTOK*EMBD];
__device__ bf16  g_hidh[(size_t)NTOK*NEXP*FFD];
__device__ bf16  g_hidl[(size_t)NTOK*NEXP*FFD];
// weight planes
__device__ bf16  g_wqkvh[(size_t)NLAYER*3*EMBD*EMBD], g_wqkvl[(size_t)NLAYER*3*EMBD*EMBD];
__device__ bf16  g_woh  [(size_t)NLAYER*EMBD*EMBD],   g_wol  [(size_t)NLAYER*EMBD*EMBD];
__device__ bf16  g_w1h  [(size_t)NLAYER*NEXP*FFD*EMBD], g_w1l[(size_t)NLAYER*NEXP*FFD*EMBD];
__device__ bf16  g_w2h  [(size_t)NLAYER*EMBD*NEXP*FFD], g_w2l[(size_t)NLAYER*EMBD*NEXP*FFD];

// ---------------- helpers -----------------------------------------------------
__device__ __forceinline__ void split2(float x, float y, uint32_t& hi, uint32_t& lo) {
    __nv_bfloat162 h, l;
    h.x = __float2bfloat16(x); h.y = __float2bfloat16(y);
    l.x = __float2bfloat16(x - __bfloat162float(h.x));
    l.y = __float2bfloat16(y - __bfloat162float(h.y));
    hi = *(uint32_t*)&h; lo = *(uint32_t*)&l;
}

#define MMA_BF16(d, a, b0, b1)                                                   \
    asm volatile("mma.sync.aligned.m16n8k16.row.col.f32.bf16.bf16.f32 "          \
                 "{%0,%1,%2,%3},{%4,%5,%6,%7},{%8,%9},{%0,%1,%2,%3};"            \
                 : "+f"(d[0]), "+f"(d[1]), "+f"(d[2]), "+f"(d[3])                 \
                 : "r"(a[0]), "r"(a[1]), "r"(a[2]), "r"(a[3]), "r"(b0), "r"(b1))

#define CP_ASYNC16(saddr, gaddr)                                                  \
    asm volatile("cp.async.cg.shared.global [%0], [%1], 16;" :: "r"(saddr), "l"(gaddr))

#define LDSM_X4(r0, r1, r2, r3, addr)                                             \
    asm volatile("ldmatrix.sync.aligned.m8n8.x4.shared.b16 {%0,%1,%2,%3}, [%4];"  \
                 : "=r"(r0), "=r"(r1), "=r"(r2), "=r"(r3) : "r"(addr))

#define LDSM_X2(r0, r1, addr)                                                     \
    asm volatile("ldmatrix.sync.aligned.m8n8.x2.shared.b16 {%0,%1}, [%2];"        \
                 : "=r"(r0), "=r"(r1) : "r"(addr))

// ---------------- fused embed+LN0 / weight-split prep -------------------------
#define WSPLIT_N  (NLAYER*4*EMBD*EMBD)          // 393216 = 3072*128
#define PREP_GRID (NTOK + WSPLIT_N/128)

__global__ void prep_kernel(const int* __restrict__ x_cat,
                            const float* __restrict__ x_num,
                            const float* __restrict__ x_eng,
                            const float* __restrict__ emb,
                            const float* __restrict__ emb_bias,
                            const float* __restrict__ emb_eng,
                            const float* __restrict__ emb_bias_eng,
                            const float* __restrict__ w,
                            const float* __restrict__ bb,
                            float* __restrict__ xout,
                            const float* __restrict__ Wqkv,
                            bf16* __restrict__ wqh, bf16* __restrict__ wql,
                            const float* __restrict__ Wo,
                            bf16* __restrict__ woh, bf16* __restrict__ wol)
{
    if (blockIdx.x >= NTOK) {
        int i = (blockIdx.x - NTOK)*128 + threadIdx.x;
        const int na = NLAYER*3*EMBD*EMBD;
        if (i < na) {
            float v = Wqkv[i];
            bf16 h = __float2bfloat16(v);
            wqh[i] = h;
            wql[i] = __float2bfloat16(v - __bfloat162float(h));
        } else {
            int j = i - na;
            float v = Wo[j];
            bf16 h = __float2bfloat16(v);
            woh[j] = h;
            wol[j] = __float2bfloat16(v - __bfloat162float(h));
        }
        return;
    }

    int tok = blockIdx.x;
    int b = tok / SEQ, t = tok % SEQ;
    int j = threadIdx.x;

    float v;
    if (t < 53) {
        int idx = x_cat[(b*51 + 50)*53 + t];
        v = emb[(size_t)idx*EMBD + j] + emb_bias[t*EMBD + j];
    } else if (t < 100) {
        int c = t - 53;
        v = emb[(size_t)(1306 + c)*EMBD + j] * x_num[(b*51 + 50)*47 + c]
            + emb_bias[t*EMBD + j];
    } else if (t < 200) {
        int c = t - 100;
        v = emb_eng[c*EMBD + j] * x_eng[b*100 + c] + emb_bias_eng[c*EMBD + j];
    } else {
        v = 0.f;
    }

    __shared__ float red[8];
    int lane = j & 31, warp = j >> 5;
    float s = v;
    #pragma unroll
    for (int o = 16; o; o >>= 1) s += __shfl_xor_sync(0xffffffffu, s, o);
    if (lane == 0) red[warp] = s;
    __syncthreads();
    float m = (red[0] + red[1] + red[2] + red[3]) * (1.f/128.f);
    float d = v - m;
    float s2 = d * d;
    #pragma unroll
    for (int o = 16; o; o >>= 1) s2 += __shfl_xor_sync(0xffffffffu, s2, o);
    if (lane == 0) red[4 + warp] = s2;
    __syncthreads();
    float var = (red[4] + red[5] + red[6] + red[7]) * (1.f/128.f);
    xout[(size_t)tok*EMBD + j] = d * rsqrtf(var + 1e-5f) * w[j] + bb[j];
}

__global__ void trans_split(const float* __restrict__ in, bf16* __restrict__ oh,
                            bf16* __restrict__ ol, int R, int C)
{
    __shared__ float tile[32][33];
    int mat = blockIdx.z;
    const float* src = in + (size_t)mat*R*C;
    int c0 = blockIdx.x*32, r0 = blockIdx.y*32;
    int x = threadIdx.x, y = threadIdx.y;
    #pragma unroll
    for (int i = 0; i < 32; i += 8)
        tile[y+i][x] = src[(size_t)(r0+y+i)*C + c0+x];
    __syncthreads();
    #pragma unroll
    for (int i = 0; i < 32; i += 8) {
        float v = tile[x][y+i];
        size_t idx = (size_t)mat*R*C + (size_t)(c0+y+i)*R + r0+x;
        bf16 h = __float2bfloat16(v);
        oh[idx] = h;
        ol[idx] = __float2bfloat16(v - __bfloat162float(h));
    }
}

// ---------------- warp-per-token LayerNorm -> bf16 hi/lo planes ---------------
__global__ void ln_warp_p(const float* __restrict__ src,
                          bf16* __restrict__ dh, bf16* __restrict__ dl,
                          const float* __restrict__ w, const float* __restrict__ bb,
                          int t0, int tstride)
{
    int lane = threadIdx.x & 31;
    int tokl = blockIdx.x * (blockDim.x >> 5) + (threadIdx.x >> 5);
    size_t tok = (size_t)t0 + (size_t)tokl * tstride;

    float4 v = *(const float4*)(src + tok*EMBD + lane*4);
    float s = v.x + v.y + v.z + v.w;
    #pragma unroll
    for (int o = 16; o; o >>= 1) s += __shfl_xor_sync(0xffffffffu, s, o);
    float m = s * (1.f/128.f);
    float dx = v.x-m, dy = v.y-m, dz = v.z-m, dw = v.w-m;
    float s2 = dx*dx + dy*dy + dz*dz + dw*dw;
    #pragma unroll
    for (int o = 16; o; o >>= 1) s2 += __shfl_xor_sync(0xffffffffu, s2, o);
    float inv = rsqrtf(s2 * (1.f/128.f) + 1e-5f);
    float4 wv = *(const float4*)(w + lane*4);
    float4 bv = *(const float4*)(bb + lane*4);
    float r0 = dx*inv*wv.x + bv.x, r1 = dy*inv*wv.y + bv.y;
    float r2 = dz*inv*wv.z + bv.z, r3 = dw*inv*wv.w + bv.w;
    uint32_t h0,l0,h1,l1;
    split2(r0, r1, h0, l0); split2(r2, r3, h1, l1);
    uint32_t* ph = (uint32_t*)(dh + tok*EMBD + lane*4);
    uint32_t* pl = (uint32_t*)(dl + tok*EMBD + lane*4);
    ph[0] = h0; ph[1] = h1; pl[0] = l0; pl[1] = l1;
}

// ---------------- fused LN2 + gate softmax -> planes --------------------------
__global__ void ln2g_p(const float* __restrict__ src,
                       bf16* __restrict__ dh, bf16* __restrict__ dl,
                       const float* __restrict__ w, const float* __restrict__ bb,
                       const float* __restrict__ Wg, const float* __restrict__ bg,
                       float* __restrict__ gate, int t0, int tstride)
{
    int lane = threadIdx.x & 31;
    int tokl = blockIdx.x * (blockDim.x >> 5) + (threadIdx.x >> 5);
    size_t tok = (size_t)t0 + (size_t)tokl * tstride;

    float4 v = *(const float4*)(src + tok*EMBD + lane*4);
    float s = v.x + v.y + v.z + v.w;
    #pragma unroll
    for (int o = 16; o; o >>= 1) s += __shfl_xor_sync(0xffffffffu, s, o);
    float m = s * (1.f/128.f);
    float dx = v.x-m, dy = v.y-m, dz = v.z-m, dw = v.w-m;
    float s2 = dx*dx + dy*dy + dz*dz + dw*dw;
    #pragma unroll
    for (int o = 16; o; o >>= 1) s2 += __shfl_xor_sync(0xffffffffu, s2, o);
    float inv = rsqrtf(s2 * (1.f/128.f) + 1e-5f);
    float4 wv = *(const float4*)(w + lane*4);
    float4 bv = *(const float4*)(bb + lane*4);
    float h[4];
    h[0] = dx*inv*wv.x + bv.x; h[1] = dy*inv*wv.y + bv.y;
    h[2] = dz*inv*wv.z + bv.z; h[3] = dw*inv*wv.w + bv.w;
    uint32_t hh0,ll0,hh1,ll1;
    split2(h[0], h[1], hh0, ll0); split2(h[2], h[3], hh1, ll1);
    uint32_t* ph = (uint32_t*)(dh + tok*EMBD + lane*4);
    uint32_t* pl = (uint32_t*)(dl + tok*EMBD + lane*4);
    ph[0] = hh0; ph[1] = hh1; pl[0] = ll0; pl[1] = ll1;

    float p[NEXP];
    #pragma unroll
    for (int e = 0; e < NEXP; e++) p[e] = 0.f;
    #pragma unroll
    for (int q = 0; q < 4; q++) {
        int j = lane*4 + q;
        #pragma unroll
        for (int e = 0; e < NEXP; e++) p[e] += h[q] * Wg[j*NEXP + e];
    }
    #pragma unroll
    for (int e = 0; e < NEXP; e++)
        #pragma unroll
        for (int o = 16; o; o >>= 1) p[e] += __shfl_xor_sync(0xffffffffu, p[e], o);
    if (lane == 0) {
        float mx = -1e30f;
        #pragma unroll
        for (int e = 0; e < NEXP; e++) { p[e] += bg[e]; mx = fmaxf(mx, p[e]); }
        float sum = 0.f;
        #pragma unroll
        for (int e = 0; e < NEXP; e++) { p[e] = __expf(p[e] - mx); sum += p[e]; }
        float is = 1.f / sum;
        #pragma unroll
        for (int e = 0; e < NEXP; e++) gate[tok*NEXP + e] = p[e] * is;
    }
}

// ---------------- bf16x3 GEMM: ldmatrix + 3-stage cp.async (R12 order) --------
#define GEMM_KP   24
#define GEMM_PL   (128*GEMM_KP)
#define GEMM_SMEM (4*3*GEMM_PL*2)   // 73728 bytes

template<int EPI>
__global__ void __launch_bounds__(256, 2)
gemm_p(const bf16* __restrict__ Ahp, const bf16* __restrict__ Alp, long rsA,
       const bf16* __restrict__ Bhp, const bf16* __restrict__ Blp,
       const float* __restrict__ bias,
       float* __restrict__ C, long rsC,
       bf16* __restrict__ Chp, bf16* __restrict__ Clp,
       const float* __restrict__ gate, long rsG,
       int K)
{
    constexpr int KP = GEMM_KP;
    constexpr int PL = GEMM_PL;
    extern __shared__ bf16 smg[];
    bf16* Ah = smg;
    bf16* Al = Ah + 3*PL;
    bf16* Bh = Al + 3*PL;
    bf16* Bl = Bh + 3*PL;

    const int tid  = threadIdx.x;
    const int warp = tid >> 5, lane = tid & 31;
    const int g = lane >> 2, r = lane & 3;
    const int wm = (warp & 3) * 32;
    const int wn = (warp >> 2) * 64;
    const int bx = blockIdx.x, by = blockIdx.y;

    float c[2][8][4];
    #pragma unroll
    for (int mi = 0; mi < 2; mi++)
        #pragma unroll
        for (int ni = 0; ni < 8; ni++)
            #pragma unroll
            for (int q = 0; q < 4; q++) c[mi][ni][q] = 0.f;

    const int crow = tid >> 1;
    const int ckseg = (tid & 1) << 3;
    const bf16* gAh = Ahp + (size_t)(by*128 + crow)*rsA + ckseg;
    const bf16* gAl = Alp + (size_t)(by*128 + crow)*rsA + ckseg;
    const bf16* gBh = Bhp + (size_t)(bx*128 + crow)*K + ckseg;
    const bf16* gBl = Blp + (size_t)(bx*128 + crow)*K + ckseg;

    uint32_t baseAh = (uint32_t)__cvta_generic_to_shared(Ah);
    uint32_t baseAl = (uint32_t)__cvta_generic_to_shared(Al);
    uint32_t baseBh = (uint32_t)__cvta_generic_to_shared(Bh);
    uint32_t baseBl = (uint32_t)__cvta_generic_to_shared(Bl);

    auto stage = [&](int k0, int s) {
        uint32_t off = (uint32_t)(s*PL + crow*KP + ckseg) * 2;
        CP_ASYNC16(baseAh + off, gAh + k0);
        CP_ASYNC16(baseAl + off, gAl + k0);
        CP_ASYNC16(baseBh + off, gBh + k0);
        CP_ASYNC16(baseBl + off, gBl + k0);
        asm volatile("cp.async.commit_group;" ::: "memory");
    };

    uint32_t a_off[2];
    #pragma unroll
    for (int mi = 0; mi < 2; mi++)
        a_off[mi] = (uint32_t)(((wm + mi*16 + (lane & 15))*KP + ((lane >> 4) << 3)) * 2);
    uint32_t b_off[4];
    #pragma unroll
    for (int p = 0; p < 4; p++)
        b_off[p] = (uint32_t)(((wn + p*16 + (lane & 7) + ((lane >> 4) << 3))*KP
                               + (((lane >> 3) & 1) << 3)) * 2);

    auto compute = [&](int s) {
        uint32_t so = (uint32_t)(s*PL*2);
        uint32_t ah[2][4], al[2][4];
        #pragma unroll
        for (int mi = 0; mi < 2; mi++) {
            LDSM_X4(ah[mi][0], ah[mi][1], ah[mi][2], ah[mi][3], baseAh + so + a_off[mi]);
            LDSM_X4(al[mi][0], al[mi][1], al[mi][2], al[mi][3], baseAl + so + a_off[mi]);
        }
        #pragma unroll
        for (int p = 0; p < 4; p++) {
            uint32_t bh[4], bl[4];
            LDSM_X4(bh[0], bh[1], bh[2], bh[3], baseBh + so + b_off[p]);
            LDSM_X4(bl[0], bl[1], bl[2], bl[3], baseBl + so + b_off[p]);
            MMA_BF16(c[0][2*p],   ah[0], bh[0], bh[1]);
            MMA_BF16(c[1][2*p],   ah[1], bh[0], bh[1]);
            MMA_BF16(c[0][2*p+1], ah[0], bh[2], bh[3]);
            MMA_BF16(c[1][2*p+1], ah[1], bh[2], bh[3]);
            MMA_BF16(c[0][2*p],   al[0], bh[0], bh[1]);
            MMA_BF16(c[1][2*p],   al[1], bh[0], bh[1]);
            MMA_BF16(c[0][2*p+1], al[0], bh[2], bh[3]);
            MMA_BF16(c[1][2*p+1], al[1], bh[2], bh[3]);
            MMA_BF16(c[0][2*p],   ah[0], bl[0], bl[1]);
            MMA_BF16(c[1][2*p],   ah[1], bl[0], bl[1]);
            MMA_BF16(c[0][2*p+1], ah[0], bl[2], bl[3]);
            MMA_BF16(c[1][2*p+1], ah[1], bl[2], bl[3]);
        }
    };

    const int nk = K >> 4;
    stage(0, 0);
    if (nk > 1) stage(16, 1);
    for (int it = 0; it < nk; ++it) {
        if (it + 1 < nk) asm volatile("cp.async.wait_group 1;" ::: "memory");
        else             asm volatile("cp.async.wait_group 0;" ::: "memory");
        __syncthreads();
        compute(it % 3);
        if (it + 2 < nk) stage((it + 2) << 4, (it + 2) % 3);
    }

    // ---------------- epilogue ----------------
    if (EPI == 4) {
        #pragma unroll
        for (int mi = 0; mi < 2; mi++)
            #pragma unroll
            for (int half = 0; half < 2; half++) {
                int m = by*128 + wm + mi*16 + g + half*8;
                float gg[NEXP];
                #pragma unroll
                for (int e = 0; e < NEXP; e++) gg[e] = gate[(size_t)m*rsG + e];
                float* crow2 = C + (size_t)m*rsC;
                #pragma unroll
                for (int ni = 0; ni < 8; ni++) {
                    int col = wn + ni*8 + 2*r;
                    float a0 = 0.f, a1 = 0.f;
                    #pragma unroll
                    for (int e = 0; e < NEXP; e++) {
                        a0 += gg[e] * bias[e*128 + col];
                        a1 += gg[e] * bias[e*128 + col + 1];
                    }
                    float2 old = *(float2*)(crow2 + col);
                    old.x += c[mi][ni][half*2 + 0] + a0;
                    old.y += c[mi][ni][half*2 + 1] + a1;
                    *(float2*)(crow2 + col) = old;
                }
            }
    } else if (EPI == 1) {
        #pragma unroll
        for (int mi = 0; mi < 2; mi++)
            #pragma unroll
            for (int half = 0; half < 2; half++) {
                int m = by*128 + wm + mi*16 + g + half*8;
                float gv = gate[(size_t)m*rsG + (bx >> 1)];
                #pragma unroll
                for (int ni = 0; ni < 8; ni++) {
                    int n = wn + ni*8 + 2*r;
                    float v0 = fmaxf(c[mi][ni][half*2+0] + bias[bx*128 + n],   0.f) * gv;
                    float v1 = fmaxf(c[mi][ni][half*2+1] + bias[bx*128 + n+1], 0.f) * gv;
                    uint32_t hi, lo;
                    split2(v0, v1, hi, lo);
                    *(uint32_t*)(Chp + (size_t)m*rsC + bx*128 + n) = hi;
                    *(uint32_t*)(Clp + (size_t)m*rsC + bx*128 + n) = lo;
                }
            }
    } else {
        #pragma unroll
        for (int mi = 0; mi < 2; mi++)
            #pragma unroll
            for (int half = 0; half < 2; half++) {
                int m = by*128 + wm + mi*16 + g + half*8;
                float* crow2 = C + (size_t)m*rsC + bx*128;
                const float* brow = bias + bx*128;
                #pragma unroll
                for (int ni = 0; ni < 8; ni++) {
                    int n = wn + ni*8 + 2*r;
                    float v0 = c[mi][ni][half*2 + 0] + brow[n];
                    float v1 = c[mi][ni][half*2 + 1] + brow[n+1];
                    if (EPI == 0) {
                        *(float2*)(crow2 + n) = make_float2(v0, v1);
                    } else {
                        float2 old = *(float2*)(crow2 + n);
                        old.x += v0; old.y += v1;
                        *(float2*)(crow2 + n) = old;
                    }
                }
            }
    }
}

// ---------------- streaming mma attention (P in registers, 3 CTAs/SM) ---------
#define KSTR 40
#define VSTR 216
#define ATTN_SMEM ((208*KSTR + 32*VSTR)*2*2)   // 60928 bytes

__global__ void __launch_bounds__(256, 3)
attn_mma(const float* __restrict__ qkv, bf16* __restrict__ ohi, bf16* __restrict__ olo,
         int qt0)
{
    extern __shared__ char smraw[];
    bf16* Kh = (bf16*)smraw;                 // [208][KSTR]   ([key][d])
    bf16* Kl = Kh + 208*KSTR;
    bf16* Vh = Kl + 208*KSTR;                // [32][VSTR]    ([d][key])
    bf16* Vl = Vh + 32*VSTR;

    const int bh0_ = blockIdx.x, b = bh0_ >> 2, h = bh0_ & 3;
    const float* base = qkv + (size_t)b*SEQ*(3*EMBD) + h*HDIM;
    const int tid = threadIdx.x, warp = tid >> 5, lane = tid & 31;
    const int g = lane >> 2, r = lane & 3;
    const float scale = 0.1767766952966369f;   // 1/sqrt(32)

    uint32_t baseKh = (uint32_t)__cvta_generic_to_shared(Kh);
    uint32_t baseKl = (uint32_t)__cvta_generic_to_shared(Kl);
    uint32_t baseVh = (uint32_t)__cvta_generic_to_shared(Vh);
    uint32_t baseVl = (uint32_t)__cvta_generic_to_shared(Vl);

    for (int idx = tid; idx < 208*32; idx += 256) {
        int t = idx >> 5, d = idx & 31;
        float kv = 0.f, vv = 0.f;
        if (t < SEQ) {
            kv = base[(size_t)t*(3*EMBD) + EMBD   + d];
            vv = base[(size_t)t*(3*EMBD) + 2*EMBD + d];
        }
        bf16 khv = __float2bfloat16(kv);
        Kh[t*KSTR + d] = khv;
        Kl[t*KSTR + d] = __float2bfloat16(kv - __bfloat162float(khv));
        bf16 vhv = __float2bfloat16(vv);
        Vh[d*VSTR + t] = vhv;
        Vl[d*VSTR + t] = __float2bfloat16(vv - __bfloat162float(vhv));
    }
    __syncthreads();

    const uint32_t kofl = (uint32_t)((((lane & 7))*KSTR + (((lane >> 3) & 3) << 3)) * 2);
    const uint32_t vofl = (uint32_t)((((lane & 7))*VSTR + (((lane >> 3) & 1) << 3)) * 2);

    for (int t = qt0 + warp; t < 13; t += 8) {
        const int qbase = t*16;

        uint32_t qh[2][4], ql[2][4];
        #pragma unroll
        for (int ks = 0; ks < 2; ks++)
            #pragma unroll
            for (int j = 0; j < 4; j++) {
                int qq = qbase + g + ((j & 1) << 3);
                if (qq > 200) qq = 200;
                int kk = ks*16 + 2*r + ((j >> 1) << 3);
                float2 v = *(const float2*)(base + (size_t)qq*(3*EMBD) + kk);
                split2(v.x*scale, v.y*scale, qh[ks][j], ql[ks][j]);
            }

        float oc[4][4];
        #pragma unroll
        for (int ni = 0; ni < 4; ni++)
            #pragma unroll
            for (int q = 0; q < 4; q++) oc[ni][q] = 0.f;
        float osum0 = 0.f, osum1 = 0.f;

        for (int kt = 0; kt < 13; kt++) {
            float s[2][4];
            #pragma unroll
            for (int p = 0; p < 2; p++) {
                s[p][0] = s[p][1] = s[p][2] = s[p][3] = 0.f;
                uint32_t ko = (uint32_t)((kt*16 + p*8)*KSTR*2) + kofl;
                uint32_t kb[4], klv[4];
                LDSM_X4(kb[0], kb[1], kb[2], kb[3], baseKh + ko);
                LDSM_X4(klv[0], klv[1], klv[2], klv[3], baseKl + ko);
                MMA_BF16(s[p], qh[0], kb[0], kb[1]);
                MMA_BF16(s[p], ql[0], kb[0], kb[1]);
                MMA_BF16(s[p], qh[0], klv[0], klv[1]);
                MMA_BF16(s[p], qh[1], kb[2], kb[3]);
                MMA_BF16(s[p], ql[1], kb[2], kb[3]);
                MMA_BF16(s[p], qh[1], klv[2], klv[3]);
            }
            #pragma unroll
            for (int p = 0; p < 2; p++) {
                int c0 = kt*16 + p*8 + 2*r;
                float e0 = (c0     <= 200) ? __expf(s[p][0]) : 0.f;
                float e1 = (c0 + 1 <= 200) ? __expf(s[p][1]) : 0.f;
                float e2 = (c0     <= 200) ? __expf(s[p][2]) : 0.f;
                float e3 = (c0 + 1 <= 200) ? __expf(s[p][3]) : 0.f;
                s[p][0] = e0; s[p][1] = e1; s[p][2] = e2; s[p][3] = e3;
                osum0 += e0 + e1;
                osum1 += e2 + e3;
            }
            uint32_t pah[4], pal[4];
            split2(s[0][0], s[0][1], pah[0], pal[0]);
            split2(s[0][2], s[0][3], pah[1], pal[1]);
            split2(s[1][0], s[1][1], pah[2], pal[2]);
            split2(s[1][2], s[1][3], pah[3], pal[3]);
            #pragma unroll
            for (int ni = 0; ni < 4; ni++) {
                uint32_t vo = (uint32_t)((ni*8*VSTR + kt*16)*2) + vofl;
                uint32_t vh0, vh1, vl0, vl1;
                LDSM_X2(vh0, vh1, baseVh + vo);
                LDSM_X2(vl0, vl1, baseVl + vo);
                MMA_BF16(oc[ni], pah, vh0, vh1);
                MMA_BF16(oc[ni], pal, vh0, vh1);
                MMA_BF16(oc[ni], pah, vl0, vl1);
            }
        }

        osum0 += __shfl_xor_sync(0xffffffffu, osum0, 1);
        osum0 += __shfl_xor_sync(0xffffffffu, osum0, 2);
        osum1 += __shfl_xor_sync(0xffffffffu, osum1, 1);
        osum1 += __shfl_xor_sync(0xffffffffu, osum1, 2);
        float inv0 = 1.f / osum0, inv1 = 1.f / osum1;

        int q0r = qbase + g, q1r = qbase + g + 8;
        #pragma unroll
        for (int ni = 0; ni < 4; ni++) {
            int d = ni*8 + 2*r;
            if (q0r <= 200) {
                uint32_t hi, lo;
                split2(oc[ni][0]*inv0, oc[ni][1]*inv0, hi, lo);
                size_t off = ((size_t)b*SEQ + q0r)*EMBD + h*HDIM + d;
                *(uint32_t*)(ohi + off) = hi;
                *(uint32_t*)(olo + off) = lo;
            }
            if (q1r <= 200) {
                uint32_t hi, lo;
                split2(oc[ni][2]*inv1, oc[ni][3]*inv1, hi, lo);
                size_t off = ((size_t)b*SEQ + q1r)*EMBD + h*HDIM + d;
                *(uint32_t*)(ohi + off) = hi;
                *(uint32_t*)(olo + off) = lo;
            }
        }
    }
}

// ---------------- output copy -------------------------------------------------
__global__ void copy_out_kernel(const float* __restrict__ x, float* __restrict__ out)
{
    int b = blockIdx.x, j = threadIdx.x;
    out[b*EMBD + j] = x[((size_t)b*SEQ + 200)*EMBD + j];
}

// ---------------- launcher ----------------------------------------------------
extern "C" void kernel_launch(void* const* d_in, const int* in_sizes, int n_in,
                              void* d_out, int out_size)
{
    (void)in_sizes; (void)n_in; (void)out_size;

    const int*   x_cat        = (const int*)  d_in[0];
    const float* x_num        = (const float*)d_in[1];
    const float* x_eng        = (const float*)d_in[2];
    const float* emb          = (const float*)d_in[3];
    const float* emb_bias     = (const float*)d_in[4];
    const float* emb_eng      = (const float*)d_in[5];
    const float* emb_bias_eng = (const float*)d_in[6];
    const float* ln0_w        = (const float*)d_in[7];
    const float* ln0_b        = (const float*)d_in[8];
    const float* ln1_w        = (const float*)d_in[9];
    const float* ln1_b        = (const float*)d_in[10];
    const float* Wqkv         = (const float*)d_in[11];
    const float* bqkv         = (const float*)d_in[12];
    const float* Wo           = (const float*)d_in[13];
    const float* bo           = (const float*)d_in[14];
    const float* ln2_w        = (const float*)d_in[15];
    const float* ln2_b        = (const float*)d_in[16];
    const float* Wg           = (const float*)d_in[17];
    const float* bg           = (const float*)d_in[18];
    const float* W1           = (const float*)d_in[19];
    const float* b1           = (const float*)d_in[20];
    const float* W2           = (const float*)d_in[21];
    const float* b2           = (const float*)d_in[22];
    float* out = (float*)d_out;

    float *px, *pqkv, *pgate;
    bf16 *phh, *phl, *poh, *pol, *phidh, *phidl;
    bf16 *pwqkvh, *pwqkvl, *pwoh, *pwol, *pw1h, *pw1l, *pw2h, *pw2l;
    cudaGetSymbolAddress((void**)&px,    g_x);
    cudaGetSymbolAddress((void**)&pqkv,  g_qkv);
    cudaGetSymbolAddress((void**)&pgate, g_gate);
    cudaGetSymbolAddress((void**)&phh,   g_hh);
    cudaGetSymbolAddress((void**)&phl,   g_hl);
    cudaGetSymbolAddress((void**)&poh,   g_oh);
    cudaGetSymbolAddress((void**)&pol,   g_ol);
    cudaGetSymbolAddress((void**)&phidh, g_hidh);
    cudaGetSymbolAddress((void**)&phidl, g_hidl);
    cudaGetSymbolAddress((void**)&pwqkvh, g_wqkvh);
    cudaGetSymbolAddress((void**)&pwqkvl, g_wqkvl);
    cudaGetSymbolAddress((void**)&pwoh,   g_woh);
    cudaGetSymbolAddress((void**)&pwol,   g_wol);
    cudaGetSymbolAddress((void**)&pw1h,   g_w1h);
    cudaGetSymbolAddress((void**)&pw1l,   g_w1l);
    cudaGetSymbolAddress((void**)&pw2h,   g_w2h);
    cudaGetSymbolAddress((void**)&pw2l,   g_w2l);

    cudaFuncSetAttribute(attn_mma, cudaFuncAttributeMaxDynamicSharedMemorySize, ATTN_SMEM);
    cudaFuncSetAttribute(gemm_p<0>, cudaFuncAttributeMaxDynamicSharedMemorySize, GEMM_SMEM);
    cudaFuncSetAttribute(gemm_p<1>, cudaFuncAttributeMaxDynamicSharedMemorySize, GEMM_SMEM);
    cudaFuncSetAttribute(gemm_p<3>, cudaFuncAttributeMaxDynamicSharedMemorySize, GEMM_SMEM);
    cudaFuncSetAttribute(gemm_p<4>, cudaFuncAttributeMaxDynamicSharedMemorySize, GEMM_SMEM);

    // launch order: #4 (ncu capture slot) = layer-0 attention
    prep_kernel<<<PREP_GRID, 128>>>(x_cat, x_num, x_eng, emb, emb_bias,
                                    emb_eng, emb_bias_eng, ln0_w, ln0_b, px,
                                    Wqkv, pwqkvh, pwqkvl, Wo, pwoh, pwol);       // 1
    ln_warp_p<<<NTOK/8, 256>>>(px, phh, phl, ln1_w, ln1_b, 0, 1);                // 2
    gemm_p<0><<<dim3(3, NTOK/128), 256, GEMM_SMEM>>>(phh, phl, EMBD,
                                              pwqkvh, pwqkvl, bqkv,
                                              pqkv, 3*EMBD, nullptr, nullptr,
                                              nullptr, 0, EMBD);                 // 3
    attn_mma<<<BATCH*NHEAD, 256, ATTN_SMEM>>>(pqkv, poh, pol, 0);                // 4 (profiled)
    trans_split<<<dim3(FFD/32, EMBD/32, NLAYER*NEXP), dim3(32,8)>>>(W1, pw1h, pw1l, EMBD, FFD);
    trans_split<<<dim3(EMBD/32, (NEXP*FFD)/32, NLAYER), dim3(32,8)>>>(W2, pw2h, pw2l, NEXP*FFD, EMBD);

    for (int i = 0; i < NLAYER; i++) {
        const bf16* wqh = pwqkvh + (size_t)i*3*EMBD*EMBD;
        const bf16* wql = pwqkvl + (size_t)i*3*EMBD*EMBD;
        const float* bqkv_i = bqkv + (size_t)i*3*EMBD;
        const bf16* woh = pwoh + (size_t)i*EMBD*EMBD;
        const bf16* wol = pwol + (size_t)i*EMBD*EMBD;
        const float* bo_i = bo + (size_t)i*EMBD;
        const float* wg_i = Wg + (size_t)i*EMBD*NEXP;
        const float* bg_i = bg + (size_t)i*NEXP;
        const bf16* w1h = pw1h + (size_t)i*NEXP*FFD*EMBD;
        const bf16* w1l = pw1l + (size_t)i*NEXP*FFD*EMBD;
        const float* b1_i = b1 + (size_t)i*NEXP*FFD;
        const bf16* w2h = pw2h + (size_t)i*EMBD*NEXP*FFD;
        const bf16* w2l = pw2l + (size_t)i*EMBD*NEXP*FFD;
        const float* b2_i = b2 + (size_t)i*NEXP*EMBD;

        if (i > 0) {
            ln_warp_p<<<NTOK/8, 256>>>(px, phh, phl, ln1_w + i*EMBD, ln1_b + i*EMBD, 0, 1);
            gemm_p<0><<<dim3(3, NTOK/128), 256, GEMM_SMEM>>>(phh, phl, EMBD, wqh, wql, bqkv_i,
                                                  pqkv, 3*EMBD, nullptr, nullptr,
                                                  nullptr, 0, EMBD);
            int qt0 = (i == NLAYER-1) ? 12 : 0;
            attn_mma<<<BATCH*NHEAD, 256, ATTN_SMEM>>>(pqkv, poh, pol, qt0);
        }

        if (i < NLAYER-1) {
            gemm_p<3><<<dim3(1, NTOK/128), 256, GEMM_SMEM>>>(poh, pol, EMBD, woh, wol, bo_i,
                                                  px, EMBD, nullptr, nullptr,
                                                  nullptr, 0, EMBD);
            ln2g_p<<<NTOK/8, 256>>>(px, phh, phl, ln2_w + i*EMBD, ln2_b + i*EMBD,
                                    wg_i, bg_i, pgate, 0, 1);
            gemm_p<1><<<dim3(10, NTOK/128), 256, GEMM_SMEM>>>(phh, phl, EMBD, w1h, w1l, b1_i,
                                                   nullptr, NEXP*FFD, phidh, phidl,
                                                   pgate, NEXP, EMBD);
            gemm_p<4><<<dim3(1, NTOK/128), 256, GEMM_SMEM>>>(phidh, phidl, NEXP*FFD, w2h, w2l, b2_i,
                                                  px, EMBD, nullptr, nullptr,
                                                  pgate, NEXP, NEXP*FFD);
        } else {
            const long rs = (long)SEQ*EMBD;
            gemm_p<3><<<dim3(1, BATCH/128), 256, GEMM_SMEM>>>(poh + (size_t)200*EMBD, pol + (size_t)200*EMBD, rs,
                                                   woh, wol, bo_i,
                                                   px + (size_t)200*EMBD, rs, nullptr, nullptr,
                                                   nullptr, 0, EMBD);
            ln2g_p<<<BATCH/8, 256>>>(px, phh, phl, ln2_w + i*EMBD, ln2_b + i*EMBD,
                                     wg_i, bg_i, pgate, 200, SEQ);
            gemm_p<1><<<dim3(10, BATCH/128), 256, GEMM_SMEM>>>(phh + (size_t)200*EMBD, phl + (size_t)200*EMBD, rs,
                                                    w1h, w1l, b1_i,
                                                    nullptr, NEXP*FFD, phidh, phidl,
                                                    pgate + (size_t)200*NEXP, (long)SEQ*NEXP, EMBD);
            gemm_p<4><<<dim3(1, BATCH/128), 256, GEMM_SMEM>>>(phidh, phidl, NEXP*FFD, w2h, w2l, b2_i,
                                                   px + (size_t)200*EMBD, rs, nullptr, nullptr,
                                                   pgate + (size_t)200*NEXP, (long)SEQ*NEXP,
                                                   NEXP*FFD);
        }
    }

    copy_out_kernel<<<BATCH, 128>>>(px, out);
}

// round 15
// speedup vs baseline: 1.0641x; 1.0216x over previous
#include <cuda_runtime.h>
#include <cuda_bf16.h>
#include <math.h>
#include <stdint.h>

#define BATCH 512
#define SEQ   201
#define EMBD  128
#define NHEAD 4
#define HDIM  32
#define FFD   256
#define NEXP  5
#define NLAYER 6
#define NTOK  (BATCH*SEQ)          // 102912

typedef __nv_bfloat16 bf16;

// ---------------- scratch (device globals; no runtime allocation) ----------
__device__ float g_x   [(size_t)NTOK*EMBD];
__device__ float g_qkv [(size_t)NTOK*3*EMBD];
__device__ float g_gate[(size_t)NTOK*NEXP];
__device__ bf16  g_hh  [(size_t)NTOK*EMBD];
__device__ bf16  g_hl  [(size_t)NTOK*EMBD];
__device__ bf16  g_oh  [(size_t)NTOK*EMBD];
__device__ bf16  g_ol  [(size_t)NTOK*EMBD];
__device__ bf16  g_hidh[(size_t)NTOK*NEXP*FFD];
__device__ bf16  g_hidl[(size_t)NTOK*NEXP*FFD];
// weight planes
__device__ bf16  g_wqkvh[(size_t)NLAYER*3*EMBD*EMBD], g_wqkvl[(size_t)NLAYER*3*EMBD*EMBD];
__device__ bf16  g_woh  [(size_t)NLAYER*EMBD*EMBD],   g_wol  [(size_t)NLAYER*EMBD*EMBD];
__device__ bf16  g_w1h  [(size_t)NLAYER*NEXP*FFD*EMBD], g_w1l[(size_t)NLAYER*NEXP*FFD*EMBD];
__device__ bf16  g_w2h  [(size_t)NLAYER*EMBD*NEXP*FFD], g_w2l[(size_t)NLAYER*EMBD*NEXP*FFD];

// ---------------- helpers -----------------------------------------------------
__device__ __forceinline__ void split2(float x, float y, uint32_t& hi, uint32_t& lo) {
    __nv_bfloat162 h, l;
    h.x = __float2bfloat16(x); h.y = __float2bfloat16(y);
    l.x = __float2bfloat16(x - __bfloat162float(h.x));
    l.y = __float2bfloat16(y - __bfloat162float(h.y));
    hi = *(uint32_t*)&h; lo = *(uint32_t*)&l;
}

#define MMA_BF16(d, a, b0, b1)                                                   \
    asm volatile("mma.sync.aligned.m16n8k16.row.col.f32.bf16.bf16.f32 "          \
                 "{%0,%1,%2,%3},{%4,%5,%6,%7},{%8,%9},{%0,%1,%2,%3};"            \
                 : "+f"(d[0]), "+f"(d[1]), "+f"(d[2]), "+f"(d[3])                 \
                 : "r"(a[0]), "r"(a[1]), "r"(a[2]), "r"(a[3]), "r"(b0), "r"(b1))

#define CP_ASYNC16(saddr, gaddr)                                                  \
    asm volatile("cp.async.cg.shared.global [%0], [%1], 16;" :: "r"(saddr), "l"(gaddr))

#define LDSM_X4(r0, r1, r2, r3, addr)                                             \
    asm volatile("ldmatrix.sync.aligned.m8n8.x4.shared.b16 {%0,%1,%2,%3}, [%4];"  \
                 : "=r"(r0), "=r"(r1), "=r"(r2), "=r"(r3) : "r"(addr))

#define LDSM_X2(r0, r1, addr)                                                     \
    asm volatile("ldmatrix.sync.aligned.m8n8.x2.shared.b16 {%0,%1}, [%2];"        \
                 : "=r"(r0), "=r"(r1) : "r"(addr))

// ---------------- fused embed+LN0 / weight-split prep -------------------------
#define WSPLIT_N  (NLAYER*4*EMBD*EMBD)          // 393216 = 3072*128
#define PREP_GRID (NTOK + WSPLIT_N/128)

__global__ void prep_kernel(const int* __restrict__ x_cat,
                            const float* __restrict__ x_num,
                            const float* __restrict__ x_eng,
                            const float* __restrict__ emb,
                            const float* __restrict__ emb_bias,
                            const float* __restrict__ emb_eng,
                            const float* __restrict__ emb_bias_eng,
                            const float* __restrict__ w,
                            const float* __restrict__ bb,
                            float* __restrict__ xout,
                            const float* __restrict__ Wqkv,
                            bf16* __restrict__ wqh, bf16* __restrict__ wql,
                            const float* __restrict__ Wo,
                            bf16* __restrict__ woh, bf16* __restrict__ wol)
{
    if (blockIdx.x >= NTOK) {
        int i = (blockIdx.x - NTOK)*128 + threadIdx.x;
        const int na = NLAYER*3*EMBD*EMBD;
        if (i < na) {
            float v = Wqkv[i];
            bf16 h = __float2bfloat16(v);
            wqh[i] = h;
            wql[i] = __float2bfloat16(v - __bfloat162float(h));
        } else {
            int j = i - na;
            float v = Wo[j];
            bf16 h = __float2bfloat16(v);
            woh[j] = h;
            wol[j] = __float2bfloat16(v - __bfloat162float(h));
        }
        return;
    }

    int tok = blockIdx.x;
    int b = tok / SEQ, t = tok % SEQ;
    int j = threadIdx.x;

    float v;
    if (t < 53) {
        int idx = x_cat[(b*51 + 50)*53 + t];
        v = emb[(size_t)idx*EMBD + j] + emb_bias[t*EMBD + j];
    } else if (t < 100) {
        int c = t - 53;
        v = emb[(size_t)(1306 + c)*EMBD + j] * x_num[(b*51 + 50)*47 + c]
            + emb_bias[t*EMBD + j];
    } else if (t < 200) {
        int c = t - 100;
        v = emb_eng[c*EMBD + j] * x_eng[b*100 + c] + emb_bias_eng[c*EMBD + j];
    } else {
        v = 0.f;
    }

    __shared__ float red[8];
    int lane = j & 31, warp = j >> 5;
    float s = v;
    #pragma unroll
    for (int o = 16; o; o >>= 1) s += __shfl_xor_sync(0xffffffffu, s, o);
    if (lane == 0) red[warp] = s;
    __syncthreads();
    float m = (red[0] + red[1] + red[2] + red[3]) * (1.f/128.f);
    float d = v - m;
    float s2 = d * d;
    #pragma unroll
    for (int o = 16; o; o >>= 1) s2 += __shfl_xor_sync(0xffffffffu, s2, o);
    if (lane == 0) red[4 + warp] = s2;
    __syncthreads();
    float var = (red[4] + red[5] + red[6] + red[7]) * (1.f/128.f);
    xout[(size_t)tok*EMBD + j] = d * rsqrtf(var + 1e-5f) * w[j] + bb[j];
}

__global__ void trans_split(const float* __restrict__ in, bf16* __restrict__ oh,
                            bf16* __restrict__ ol, int R, int C)
{
    __shared__ float tile[32][33];
    int mat = blockIdx.z;
    const float* src = in + (size_t)mat*R*C;
    int c0 = blockIdx.x*32, r0 = blockIdx.y*32;
    int x = threadIdx.x, y = threadIdx.y;
    #pragma unroll
    for (int i = 0; i < 32; i += 8)
        tile[y+i][x] = src[(size_t)(r0+y+i)*C + c0+x];
    __syncthreads();
    #pragma unroll
    for (int i = 0; i < 32; i += 8) {
        float v = tile[x][y+i];
        size_t idx = (size_t)mat*R*C + (size_t)(c0+y+i)*R + r0+x;
        bf16 h = __float2bfloat16(v);
        oh[idx] = h;
        ol[idx] = __float2bfloat16(v - __bfloat162float(h));
    }
}

// ---------------- warp-per-token LayerNorm -> bf16 hi/lo planes ---------------
__global__ void ln_warp_p(const float* __restrict__ src,
                          bf16* __restrict__ dh, bf16* __restrict__ dl,
                          const float* __restrict__ w, const float* __restrict__ bb,
                          int t0, int tstride)
{
    int lane = threadIdx.x & 31;
    int tokl = blockIdx.x * (blockDim.x >> 5) + (threadIdx.x >> 5);
    size_t tok = (size_t)t0 + (size_t)tokl * tstride;

    float4 v = *(const float4*)(src + tok*EMBD + lane*4);
    float s = v.x + v.y + v.z + v.w;
    #pragma unroll
    for (int o = 16; o; o >>= 1) s += __shfl_xor_sync(0xffffffffu, s, o);
    float m = s * (1.f/128.f);
    float dx = v.x-m, dy = v.y-m, dz = v.z-m, dw = v.w-m;
    float s2 = dx*dx + dy*dy + dz*dz + dw*dw;
    #pragma unroll
    for (int o = 16; o; o >>= 1) s2 += __shfl_xor_sync(0xffffffffu, s2, o);
    float inv = rsqrtf(s2 * (1.f/128.f) + 1e-5f);
    float4 wv = *(const float4*)(w + lane*4);
    float4 bv = *(const float4*)(bb + lane*4);
    float r0 = dx*inv*wv.x + bv.x, r1 = dy*inv*wv.y + bv.y;
    float r2 = dz*inv*wv.z + bv.z, r3 = dw*inv*wv.w + bv.w;
    uint32_t h0,l0,h1,l1;
    split2(r0, r1, h0, l0); split2(r2, r3, h1, l1);
    uint32_t* ph = (uint32_t*)(dh + tok*EMBD + lane*4);
    uint32_t* pl = (uint32_t*)(dl + tok*EMBD + lane*4);
    ph[0] = h0; ph[1] = h1; pl[0] = l0; pl[1] = l1;
}

// ---------------- fused LN2 + gate softmax -> planes (last layer only) --------
__global__ void ln2g_p(const float* __restrict__ src,
                       bf16* __restrict__ dh, bf16* __restrict__ dl,
                       const float* __restrict__ w, const float* __restrict__ bb,
                       const float* __restrict__ Wg, const float* __restrict__ bg,
                       float* __restrict__ gate, int t0, int tstride)
{
    int lane = threadIdx.x & 31;
    int tokl = blockIdx.x * (blockDim.x >> 5) + (threadIdx.x >> 5);
    size_t tok = (size_t)t0 + (size_t)tokl * tstride;

    float4 v = *(const float4*)(src + tok*EMBD + lane*4);
    float s = v.x + v.y + v.z + v.w;
    #pragma unroll
    for (int o = 16; o; o >>= 1) s += __shfl_xor_sync(0xffffffffu, s, o);
    float m = s * (1.f/128.f);
    float dx = v.x-m, dy = v.y-m, dz = v.z-m, dw = v.w-m;
    float s2 = dx*dx + dy*dy + dz*dz + dw*dw;
    #pragma unroll
    for (int o = 16; o; o >>= 1) s2 += __shfl_xor_sync(0xffffffffu, s2, o);
    float inv = rsqrtf(s2 * (1.f/128.f) + 1e-5f);
    float4 wv = *(const float4*)(w + lane*4);
    float4 bv = *(const float4*)(bb + lane*4);
    float h[4];
    h[0] = dx*inv*wv.x + bv.x; h[1] = dy*inv*wv.y + bv.y;
    h[2] = dz*inv*wv.z + bv.z; h[3] = dw*inv*wv.w + bv.w;
    uint32_t hh0,ll0,hh1,ll1;
    split2(h[0], h[1], hh0, ll0); split2(h[2], h[3], hh1, ll1);
    uint32_t* ph = (uint32_t*)(dh + tok*EMBD + lane*4);
    uint32_t* pl = (uint32_t*)(dl + tok*EMBD + lane*4);
    ph[0] = hh0; ph[1] = hh1; pl[0] = ll0; pl[1] = ll1;

    float p[NEXP];
    #pragma unroll
    for (int e = 0; e < NEXP; e++) p[e] = 0.f;
    #pragma unroll
    for (int q = 0; q < 4; q++) {
        int j = lane*4 + q;
        #pragma unroll
        for (int e = 0; e < NEXP; e++) p[e] += h[q] * Wg[j*NEXP + e];
    }
    #pragma unroll
    for (int e = 0; e < NEXP; e++)
        #pragma unroll
        for (int o = 16; o; o >>= 1) p[e] += __shfl_xor_sync(0xffffffffu, p[e], o);
    if (lane == 0) {
        float mx = -1e30f;
        #pragma unroll
        for (int e = 0; e < NEXP; e++) { p[e] += bg[e]; mx = fmaxf(mx, p[e]); }
        float sum = 0.f;
        #pragma unroll
        for (int e = 0; e < NEXP; e++) { p[e] = __expf(p[e] - mx); sum += p[e]; }
        float is = 1.f / sum;
        #pragma unroll
        for (int e = 0; e < NEXP; e++) gate[tok*NEXP + e] = p[e] * is;
    }
}

// ---------------- bf16x3 GEMM: ldmatrix + 3-stage cp.async --------------------
// EPI 0: C = acc+bias ; EPI 1: planes = split(relu(acc+bias)*gate[m][bx>>1])
// EPI 3: C += acc+bias ; EPI 4: C += acc + sum_e gate[m][e]*bias[e*128+n]
// EPI 5: (N=128,bx=0) x = C+acc+bias; LN2(x)->planes; gate softmax -> gate
// EPI 6: (N=128,bx=0) x = C+acc+sum_e g*bias; LN1next(x)->planes
#define GEMM_KP   24
#define GEMM_PL   (128*GEMM_KP)
#define GEMM_SMEM (4*3*GEMM_PL*2)   // 73728 bytes
#define EPADC 132                   // fp32 row stride in epilogue buffer

template<int EPI>
__global__ void __launch_bounds__(256, 2)
gemm_p(const bf16* __restrict__ Ahp, const bf16* __restrict__ Alp, long rsA,
       const bf16* __restrict__ Bhp, const bf16* __restrict__ Blp,
       const float* __restrict__ bias,
       float* __restrict__ C, long rsC,
       bf16* __restrict__ Chp, bf16* __restrict__ Clp,
       float* __restrict__ gate, long rsG,
       int K,
       const float* __restrict__ lnw, const float* __restrict__ lnb,
       const float* __restrict__ wg, const float* __restrict__ bgp)
{
    constexpr int KP = GEMM_KP;
    constexpr int PL = GEMM_PL;
    extern __shared__ bf16 smg[];
    bf16* Ah = smg;
    bf16* Al = Ah + 3*PL;
    bf16* Bh = Al + 3*PL;
    bf16* Bl = Bh + 3*PL;

    const int tid  = threadIdx.x;
    const int warp = tid >> 5, lane = tid & 31;
    const int g = lane >> 2, r = lane & 3;
    const int wm = (warp & 3) * 32;
    const int wn = (warp >> 2) * 64;
    const int bx = blockIdx.x, by = blockIdx.y;

    float c[2][8][4];
    #pragma unroll
    for (int mi = 0; mi < 2; mi++)
        #pragma unroll
        for (int ni = 0; ni < 8; ni++)
            #pragma unroll
            for (int q = 0; q < 4; q++) c[mi][ni][q] = 0.f;

    const int crow = tid >> 1;
    const int ckseg = (tid & 1) << 3;
    const bf16* gAh = Ahp + (size_t)(by*128 + crow)*rsA + ckseg;
    const bf16* gAl = Alp + (size_t)(by*128 + crow)*rsA + ckseg;
    const bf16* gBh = Bhp + (size_t)(bx*128 + crow)*K + ckseg;
    const bf16* gBl = Blp + (size_t)(bx*128 + crow)*K + ckseg;

    uint32_t baseAh = (uint32_t)__cvta_generic_to_shared(Ah);
    uint32_t baseAl = (uint32_t)__cvta_generic_to_shared(Al);
    uint32_t baseBh = (uint32_t)__cvta_generic_to_shared(Bh);
    uint32_t baseBl = (uint32_t)__cvta_generic_to_shared(Bl);

    auto stage = [&](int k0, int s) {
        uint32_t off = (uint32_t)(s*PL + crow*KP + ckseg) * 2;
        CP_ASYNC16(baseAh + off, gAh + k0);
        CP_ASYNC16(baseAl + off, gAl + k0);
        CP_ASYNC16(baseBh + off, gBh + k0);
        CP_ASYNC16(baseBl + off, gBl + k0);
        asm volatile("cp.async.commit_group;" ::: "memory");
    };

    uint32_t a_off[2];
    #pragma unroll
    for (int mi = 0; mi < 2; mi++)
        a_off[mi] = (uint32_t)(((wm + mi*16 + (lane & 15))*KP + ((lane >> 4) << 3)) * 2);
    uint32_t b_off[4];
    #pragma unroll
    for (int p = 0; p < 4; p++)
        b_off[p] = (uint32_t)(((wn + p*16 + (lane & 7) + ((lane >> 4) << 3))*KP
                               + (((lane >> 3) & 1) << 3)) * 2);

    auto compute = [&](int s) {
        uint32_t so = (uint32_t)(s*PL*2);
        uint32_t ah[2][4], al[2][4];
        #pragma unroll
        for (int mi = 0; mi < 2; mi++) {
            LDSM_X4(ah[mi][0], ah[mi][1], ah[mi][2], ah[mi][3], baseAh + so + a_off[mi]);
            LDSM_X4(al[mi][0], al[mi][1], al[mi][2], al[mi][3], baseAl + so + a_off[mi]);
        }
        #pragma unroll
        for (int p = 0; p < 4; p++) {
            uint32_t bh[4], bl[4];
            LDSM_X4(bh[0], bh[1], bh[2], bh[3], baseBh + so + b_off[p]);
            LDSM_X4(bl[0], bl[1], bl[2], bl[3], baseBl + so + b_off[p]);
            MMA_BF16(c[0][2*p],   ah[0], bh[0], bh[1]);
            MMA_BF16(c[1][2*p],   ah[1], bh[0], bh[1]);
            MMA_BF16(c[0][2*p+1], ah[0], bh[2], bh[3]);
            MMA_BF16(c[1][2*p+1], ah[1], bh[2], bh[3]);
            MMA_BF16(c[0][2*p],   al[0], bh[0], bh[1]);
            MMA_BF16(c[1][2*p],   al[1], bh[0], bh[1]);
            MMA_BF16(c[0][2*p+1], al[0], bh[2], bh[3]);
            MMA_BF16(c[1][2*p+1], al[1], bh[2], bh[3]);
            MMA_BF16(c[0][2*p],   ah[0], bl[0], bl[1]);
            MMA_BF16(c[1][2*p],   ah[1], bl[0], bl[1]);
            MMA_BF16(c[0][2*p+1], ah[0], bl[2], bl[3]);
            MMA_BF16(c[1][2*p+1], ah[1], bl[2], bl[3]);
        }
    };

    const int nk = K >> 4;
    stage(0, 0);
    if (nk > 1) stage(16, 1);
    for (int it = 0; it < nk; ++it) {
        if (it + 1 < nk) asm volatile("cp.async.wait_group 1;" ::: "memory");
        else             asm volatile("cp.async.wait_group 0;" ::: "memory");
        __syncthreads();
        compute(it % 3);
        if (it + 2 < nk) stage((it + 2) << 4, (it + 2) % 3);
    }

    // ---------------- epilogue ----------------
    if (EPI == 5 || EPI == 6) {
        // N==128, bx==0: CTA owns 128 complete rows. Stash v in smem, then
        // warp-per-16-rows LayerNorm (+ gate softmax for EPI 5).
        __syncthreads();                      // mainloop smem reads done
        float* buf = (float*)smg;             // [128][EPADC] = 67.6 KB < 73.7 KB
        #pragma unroll
        for (int mi = 0; mi < 2; mi++)
            #pragma unroll
            for (int half = 0; half < 2; half++) {
                int row = wm + mi*16 + g + half*8;
                int m = by*128 + row;
                if (EPI == 5) {
                    #pragma unroll
                    for (int ni = 0; ni < 8; ni++) {
                        int col = wn + ni*8 + 2*r;
                        float2 old = *(float2*)(C + (size_t)m*rsC + col);
                        float2 v;
                        v.x = old.x + c[mi][ni][half*2+0] + bias[col];
                        v.y = old.y + c[mi][ni][half*2+1] + bias[col+1];
                        *(float2*)&buf[row*EPADC + col] = v;
                    }
                } else {
                    float gg[NEXP];
                    #pragma unroll
                    for (int e = 0; e < NEXP; e++) gg[e] = gate[(size_t)m*rsG + e];
                    #pragma unroll
                    for (int ni = 0; ni < 8; ni++) {
                        int col = wn + ni*8 + 2*r;
                        float a0 = 0.f, a1 = 0.f;
                        #pragma unroll
                        for (int e = 0; e < NEXP; e++) {
                            a0 += gg[e] * bias[e*128 + col];
                            a1 += gg[e] * bias[e*128 + col + 1];
                        }
                        float2 old = *(float2*)(C + (size_t)m*rsC + col);
                        float2 v;
                        v.x = old.x + c[mi][ni][half*2+0] + a0;
                        v.y = old.y + c[mi][ni][half*2+1] + a1;
                        *(float2*)&buf[row*EPADC + col] = v;
                    }
                }
            }
        __syncthreads();
        for (int i = 0; i < 16; i++) {
            int row = warp*16 + i;
            int m = by*128 + row;
            float4 v = *(float4*)&buf[row*EPADC + lane*4];
            // write x (pre-LN residual)
            *(float4*)(C + (size_t)m*rsC + lane*4) = v;
            // LayerNorm (same lane-4 + shfl pattern as ln_warp_p)
            float s = v.x + v.y + v.z + v.w;
            #pragma unroll
            for (int o = 16; o; o >>= 1) s += __shfl_xor_sync(0xffffffffu, s, o);
            float mn = s * (1.f/128.f);
            float dx = v.x-mn, dy = v.y-mn, dz = v.z-mn, dw = v.w-mn;
            float s2 = dx*dx + dy*dy + dz*dz + dw*dw;
            #pragma unroll
            for (int o = 16; o; o >>= 1) s2 += __shfl_xor_sync(0xffffffffu, s2, o);
            float inv = rsqrtf(s2 * (1.f/128.f) + 1e-5f);
            float4 wv = *(const float4*)(lnw + lane*4);
            float4 bv = *(const float4*)(lnb + lane*4);
            float h[4];
            h[0] = dx*inv*wv.x + bv.x; h[1] = dy*inv*wv.y + bv.y;
            h[2] = dz*inv*wv.z + bv.z; h[3] = dw*inv*wv.w + bv.w;
            uint32_t hh0,ll0,hh1,ll1;
            split2(h[0], h[1], hh0, ll0); split2(h[2], h[3], hh1, ll1);
            uint32_t* ph = (uint32_t*)(Chp + (size_t)m*rsC + lane*4);
            uint32_t* pl = (uint32_t*)(Clp + (size_t)m*rsC + lane*4);
            ph[0] = hh0; ph[1] = hh1; pl[0] = ll0; pl[1] = ll1;
            if (EPI == 5) {
                float p[NEXP];
                #pragma unroll
                for (int e = 0; e < NEXP; e++) p[e] = 0.f;
                #pragma unroll
                for (int q = 0; q < 4; q++) {
                    int j = lane*4 + q;
                    #pragma unroll
                    for (int e = 0; e < NEXP; e++) p[e] += h[q] * wg[j*NEXP + e];
                }
                #pragma unroll
                for (int e = 0; e < NEXP; e++)
                    #pragma unroll
                    for (int o = 16; o; o >>= 1) p[e] += __shfl_xor_sync(0xffffffffu, p[e], o);
                if (lane == 0) {
                    float mx = -1e30f;
                    #pragma unroll
                    for (int e = 0; e < NEXP; e++) { p[e] += bgp[e]; mx = fmaxf(mx, p[e]); }
                    float sum = 0.f;
                    #pragma unroll
                    for (int e = 0; e < NEXP; e++) { p[e] = __expf(p[e] - mx); sum += p[e]; }
                    float is = 1.f / sum;
                    #pragma unroll
                    for (int e = 0; e < NEXP; e++) gate[(size_t)m*NEXP + e] = p[e] * is;
                }
            }
        }
    } else if (EPI == 4) {
        #pragma unroll
        for (int mi = 0; mi < 2; mi++)
            #pragma unroll
            for (int half = 0; half < 2; half++) {
                int m = by*128 + wm + mi*16 + g + half*8;
                float gg[NEXP];
                #pragma unroll
                for (int e = 0; e < NEXP; e++) gg[e] = gate[(size_t)m*rsG + e];
                float* crow2 = C + (size_t)m*rsC;
                #pragma unroll
                for (int ni = 0; ni < 8; ni++) {
                    int col = wn + ni*8 + 2*r;
                    float a0 = 0.f, a1 = 0.f;
                    #pragma unroll
                    for (int e = 0; e < NEXP; e++) {
                        a0 += gg[e] * bias[e*128 + col];
                        a1 += gg[e] * bias[e*128 + col + 1];
                    }
                    float2 old = *(float2*)(crow2 + col);
                    old.x += c[mi][ni][half*2 + 0] + a0;
                    old.y += c[mi][ni][half*2 + 1] + a1;
                    *(float2*)(crow2 + col) = old;
                }
            }
    } else if (EPI == 1) {
        #pragma unroll
        for (int mi = 0; mi < 2; mi++)
            #pragma unroll
            for (int half = 0; half < 2; half++) {
                int m = by*128 + wm + mi*16 + g + half*8;
                float gv = gate[(size_t)m*rsG + (bx >> 1)];
                #pragma unroll
                for (int ni = 0; ni < 8; ni++) {
                    int n = wn + ni*8 + 2*r;
                    float v0 = fmaxf(c[mi][ni][half*2+0] + bias[bx*128 + n],   0.f) * gv;
                    float v1 = fmaxf(c[mi][ni][half*2+1] + bias[bx*128 + n+1], 0.f) * gv;
                    uint32_t hi, lo;
                    split2(v0, v1, hi, lo);
                    *(uint32_t*)(Chp + (size_t)m*rsC + bx*128 + n) = hi;
                    *(uint32_t*)(Clp + (size_t)m*rsC + bx*128 + n) = lo;
                }
            }
    } else {
        #pragma unroll
        for (int mi = 0; mi < 2; mi++)
            #pragma unroll
            for (int half = 0; half < 2; half++) {
                int m = by*128 + wm + mi*16 + g + half*8;
                float* crow2 = C + (size_t)m*rsC + bx*128;
                const float* brow = bias + bx*128;
                #pragma unroll
                for (int ni = 0; ni < 8; ni++) {
                    int n = wn + ni*8 + 2*r;
                    float v0 = c[mi][ni][half*2 + 0] + brow[n];
                    float v1 = c[mi][ni][half*2 + 1] + brow[n+1];
                    if (EPI == 0) {
                        *(float2*)(crow2 + n) = make_float2(v0, v1);
                    } else {
                        float2 old = *(float2*)(crow2 + n);
                        old.x += v0; old.y += v1;
                        *(float2*)(crow2 + n) = old;
                    }
                }
            }
    }
}

// ---------------- streaming mma attention (P in registers, 3 CTAs/SM) ---------
#define KSTR 40
#define VSTR 216
#define ATTN_SMEM ((208*KSTR + 32*VSTR)*2*2)   // 60928 bytes

__global__ void __launch_bounds__(256, 3)
attn_mma(const float* __restrict__ qkv, bf16* __restrict__ ohi, bf16* __restrict__ olo,
         int qt0)
{
    extern __shared__ char smraw[];
    bf16* Kh = (bf16*)smraw;                 // [208][KSTR]   ([key][d])
    bf16* Kl = Kh + 208*KSTR;
    bf16* Vh = Kl + 208*KSTR;                // [32][VSTR]    ([d][key])
    bf16* Vl = Vh + 32*VSTR;

    const int bh0_ = blockIdx.x, b = bh0_ >> 2, h = bh0_ & 3;
    const float* base = qkv + (size_t)b*SEQ*(3*EMBD) + h*HDIM;
    const int tid = threadIdx.x, warp = tid >> 5, lane = tid & 31;
    const int g = lane >> 2, r = lane & 3;
    const float scale = 0.1767766952966369f;   // 1/sqrt(32)

    uint32_t baseKh = (uint32_t)__cvta_generic_to_shared(Kh);
    uint32_t baseKl = (uint32_t)__cvta_generic_to_shared(Kl);
    uint32_t baseVh = (uint32_t)__cvta_generic_to_shared(Vh);
    uint32_t baseVl = (uint32_t)__cvta_generic_to_shared(Vl);

    for (int idx = tid; idx < 208*32; idx += 256) {
        int t = idx >> 5, d = idx & 31;
        float kv = 0.f, vv = 0.f;
        if (t < SEQ) {
            kv = base[(size_t)t*(3*EMBD) + EMBD   + d];
            vv = base[(size_t)t*(3*EMBD) + 2*EMBD + d];
        }
        bf16 khv = __float2bfloat16(kv);
        Kh[t*KSTR + d] = khv;
        Kl[t*KSTR + d] = __float2bfloat16(kv - __bfloat162float(khv));
        bf16 vhv = __float2bfloat16(vv);
        Vh[d*VSTR + t] = vhv;
        Vl[d*VSTR + t] = __float2bfloat16(vv - __bfloat162float(vhv));
    }
    __syncthreads();

    const uint32_t kofl = (uint32_t)((((lane & 7))*KSTR + (((lane >> 3) & 3) << 3)) * 2);
    const uint32_t vofl = (uint32_t)((((lane & 7))*VSTR + (((lane >> 3) & 1) << 3)) * 2);

    for (int t = qt0 + warp; t < 13; t += 8) {
        const int qbase = t*16;

        uint32_t qh[2][4], ql[2][4];
        #pragma unroll
        for (int ks = 0; ks < 2; ks++)
            #pragma unroll
            for (int j = 0; j < 4; j++) {
                int qq = qbase + g + ((j & 1) << 3);
                if (qq > 200) qq = 200;
                int kk = ks*16 + 2*r + ((j >> 1) << 3);
                float2 v = *(const float2*)(base + (size_t)qq*(3*EMBD) + kk);
                split2(v.x*scale, v.y*scale, qh[ks][j], ql[ks][j]);
            }

        float oc[4][4];
        #pragma unroll
        for (int ni = 0; ni < 4; ni++)
            #pragma unroll
            for (int q = 0; q < 4; q++) oc[ni][q] = 0.f;
        float osum0 = 0.f, osum1 = 0.f;

        for (int kt = 0; kt < 13; kt++) {
            float s[2][4];
            #pragma unroll
            for (int p = 0; p < 2; p++) {
                s[p][0] = s[p][1] = s[p][2] = s[p][3] = 0.f;
                uint32_t ko = (uint32_t)((kt*16 + p*8)*KSTR*2) + kofl;
                uint32_t kb[4], klv[4];
                LDSM_X4(kb[0], kb[1], kb[2], kb[3], baseKh + ko);
                LDSM_X4(klv[0], klv[1], klv[2], klv[3], baseKl + ko);
                MMA_BF16(s[p], qh[0], kb[0], kb[1]);
                MMA_BF16(s[p], ql[0], kb[0], kb[1]);
                MMA_BF16(s[p], qh[0], klv[0], klv[1]);
                MMA_BF16(s[p], qh[1], kb[2], kb[3]);
                MMA_BF16(s[p], ql[1], kb[2], kb[3]);
                MMA_BF16(s[p], qh[1], klv[2], klv[3]);
            }
            #pragma unroll
            for (int p = 0; p < 2; p++) {
                int c0 = kt*16 + p*8 + 2*r;
                float e0 = (c0     <= 200) ? __expf(s[p][0]) : 0.f;
                float e1 = (c0 + 1 <= 200) ? __expf(s[p][1]) : 0.f;
                float e2 = (c0     <= 200) ? __expf(s[p][2]) : 0.f;
                float e3 = (c0 + 1 <= 200) ? __expf(s[p][3]) : 0.f;
                s[p][0] = e0; s[p][1] = e1; s[p][2] = e2; s[p][3] = e3;
                osum0 += e0 + e1;
                osum1 += e2 + e3;
            }
            uint32_t pah[4], pal[4];
            split2(s[0][0], s[0][1], pah[0], pal[0]);
            split2(s[0][2], s[0][3], pah[1], pal[1]);
            split2(s[1][0], s[1][1], pah[2], pal[2]);
            split2(s[1][2], s[1][3], pah[3], pal[3]);
            #pragma unroll
            for (int ni = 0; ni < 4; ni++) {
                uint32_t vo = (uint32_t)((ni*8*VSTR + kt*16)*2) + vofl;
                uint32_t vh0, vh1, vl0, vl1;
                LDSM_X2(vh0, vh1, baseVh + vo);
                LDSM_X2(vl0, vl1, baseVl + vo);
                MMA_BF16(oc[ni], pah, vh0, vh1);
                MMA_BF16(oc[ni], pal, vh0, vh1);
                MMA_BF16(oc[ni], pah, vl0, vl1);
            }
        }

        osum0 += __shfl_xor_sync(0xffffffffu, osum0, 1);
        osum0 += __shfl_xor_sync(0xffffffffu, osum0, 2);
        osum1 += __shfl_xor_sync(0xffffffffu, osum1, 1);
        osum1 += __shfl_xor_sync(0xffffffffu, osum1, 2);
        float inv0 = 1.f / osum0, inv1 = 1.f / osum1;

        int q0r = qbase + g, q1r = qbase + g + 8;
        #pragma unroll
        for (int ni = 0; ni < 4; ni++) {
            int d = ni*8 + 2*r;
            if (q0r <= 200) {
                uint32_t hi, lo;
                split2(oc[ni][0]*inv0, oc[ni][1]*inv0, hi, lo);
                size_t off = ((size_t)b*SEQ + q0r)*EMBD + h*HDIM + d;
                *(uint32_t*)(ohi + off) = hi;
                *(uint32_t*)(olo + off) = lo;
            }
            if (q1r <= 200) {
                uint32_t hi, lo;
                split2(oc[ni][2]*inv1, oc[ni][3]*inv1, hi, lo);
                size_t off = ((size_t)b*SEQ + q1r)*EMBD + h*HDIM + d;
                *(uint32_t*)(ohi + off) = hi;
                *(uint32_t*)(olo + off) = lo;
            }
        }
    }
}

// ---------------- output copy -------------------------------------------------
__global__ void copy_out_kernel(const float* __restrict__ x, float* __restrict__ out)
{
    int b = blockIdx.x, j = threadIdx.x;
    out[b*EMBD + j] = x[((size_t)b*SEQ + 200)*EMBD + j];
}

// ---------------- launcher ----------------------------------------------------
extern "C" void kernel_launch(void* const* d_in, const int* in_sizes, int n_in,
                              void* d_out, int out_size)
{
    (void)in_sizes; (void)n_in; (void)out_size;

    const int*   x_cat        = (const int*)  d_in[0];
    const float* x_num        = (const float*)d_in[1];
    const float* x_eng        = (const float*)d_in[2];
    const float* emb          = (const float*)d_in[3];
    const float* emb_bias     = (const float*)d_in[4];
    const float* emb_eng      = (const float*)d_in[5];
    const float* emb_bias_eng = (const float*)d_in[6];
    const float* ln0_w        = (const float*)d_in[7];
    const float* ln0_b        = (const float*)d_in[8];
    const float* ln1_w        = (const float*)d_in[9];
    const float* ln1_b        = (const float*)d_in[10];
    const float* Wqkv         = (const float*)d_in[11];
    const float* bqkv         = (const float*)d_in[12];
    const float* Wo           = (const float*)d_in[13];
    const float* bo           = (const float*)d_in[14];
    const float* ln2_w        = (const float*)d_in[15];
    const float* ln2_b        = (const float*)d_in[16];
    const float* Wg           = (const float*)d_in[17];
    const float* bg           = (const float*)d_in[18];
    const float* W1           = (const float*)d_in[19];
    const float* b1           = (const float*)d_in[20];
    const float* W2           = (const float*)d_in[21];
    const float* b2           = (const float*)d_in[22];
    float* out = (float*)d_out;

    float *px, *pqkv, *pgate;
    bf16 *phh, *phl, *poh, *pol, *phidh, *phidl;
    bf16 *pwqkvh, *pwqkvl, *pwoh, *pwol, *pw1h, *pw1l, *pw2h, *pw2l;
    cudaGetSymbolAddress((void**)&px,    g_x);
    cudaGetSymbolAddress((void**)&pqkv,  g_qkv);
    cudaGetSymbolAddress((void**)&pgate, g_gate);
    cudaGetSymbolAddress((void**)&phh,   g_hh);
    cudaGetSymbolAddress((void**)&phl,   g_hl);
    cudaGetSymbolAddress((void**)&poh,   g_oh);
    cudaGetSymbolAddress((void**)&pol,   g_ol);
    cudaGetSymbolAddress((void**)&phidh, g_hidh);
    cudaGetSymbolAddress((void**)&phidl, g_hidl);
    cudaGetSymbolAddress((void**)&pwqkvh, g_wqkvh);
    cudaGetSymbolAddress((void**)&pwqkvl, g_wqkvl);
    cudaGetSymbolAddress((void**)&pwoh,   g_woh);
    cudaGetSymbolAddress((void**)&pwol,   g_wol);
    cudaGetSymbolAddress((void**)&pw1h,   g_w1h);
    cudaGetSymbolAddress((void**)&pw1l,   g_w1l);
    cudaGetSymbolAddress((void**)&pw2h,   g_w2h);
    cudaGetSymbolAddress((void**)&pw2l,   g_w2l);

    cudaFuncSetAttribute(attn_mma, cudaFuncAttributeMaxDynamicSharedMemorySize, ATTN_SMEM);
    cudaFuncSetAttribute(gemm_p<0>, cudaFuncAttributeMaxDynamicSharedMemorySize, GEMM_SMEM);
    cudaFuncSetAttribute(gemm_p<1>, cudaFuncAttributeMaxDynamicSharedMemorySize, GEMM_SMEM);
    cudaFuncSetAttribute(gemm_p<3>, cudaFuncAttributeMaxDynamicSharedMemorySize, GEMM_SMEM);
    cudaFuncSetAttribute(gemm_p<4>, cudaFuncAttributeMaxDynamicSharedMemorySize, GEMM_SMEM);
    cudaFuncSetAttribute(gemm_p<5>, cudaFuncAttributeMaxDynamicSharedMemorySize, GEMM_SMEM);
    cudaFuncSetAttribute(gemm_p<6>, cudaFuncAttributeMaxDynamicSharedMemorySize, GEMM_SMEM);

    // launch order: #4 (ncu capture slot) = layer-0 attention
    prep_kernel<<<PREP_GRID, 128>>>(x_cat, x_num, x_eng, emb, emb_bias,
                                    emb_eng, emb_bias_eng, ln0_w, ln0_b, px,
                                    Wqkv, pwqkvh, pwqkvl, Wo, pwoh, pwol);       // 1
    ln_warp_p<<<NTOK/8, 256>>>(px, phh, phl, ln1_w, ln1_b, 0, 1);                // 2
    gemm_p<0><<<dim3(3, NTOK/128), 256, GEMM_SMEM>>>(phh, phl, EMBD,
                                              pwqkvh, pwqkvl, bqkv,
                                              pqkv, 3*EMBD, nullptr, nullptr,
                                              nullptr, 0, EMBD,
                                              nullptr, nullptr, nullptr, nullptr); // 3
    attn_mma<<<BATCH*NHEAD, 256, ATTN_SMEM>>>(pqkv, poh, pol, 0);                // 4 (profiled)
    trans_split<<<dim3(FFD/32, EMBD/32, NLAYER*NEXP), dim3(32,8)>>>(W1, pw1h, pw1l, EMBD, FFD);
    trans_split<<<dim3(EMBD/32, (NEXP*FFD)/32, NLAYER), dim3(32,8)>>>(W2, pw2h, pw2l, NEXP*FFD, EMBD);

    for (int i = 0; i < NLAYER; i++) {
        const bf16* wqh = pwqkvh + (size_t)i*3*EMBD*EMBD;
        const bf16* wql = pwqkvl + (size_t)i*3*EMBD*EMBD;
        const float* bqkv_i = bqkv + (size_t)i*3*EMBD;
        const bf16* woh = pwoh + (size_t)i*EMBD*EMBD;
        const bf16* wol = pwol + (size_t)i*EMBD*EMBD;
        const float* bo_i = bo + (size_t)i*EMBD;
        const float* wg_i = Wg + (size_t)i*EMBD*NEXP;
        const float* bg_i = bg + (size_t)i*NEXP;
        const bf16* w1h = pw1h + (size_t)i*NEXP*FFD*EMBD;
        const bf16* w1l = pw1l + (size_t)i*NEXP*FFD*EMBD;
        const float* b1_i = b1 + (size_t)i*NEXP*FFD;
        const bf16* w2h = pw2h + (size_t)i*EMBD*NEXP*FFD;
        const bf16* w2l = pw2l + (size_t)i*EMBD*NEXP*FFD;
        const float* b2_i = b2 + (size_t)i*NEXP*EMBD;

        if (i > 0) {
            // ln1 planes for this layer were produced by layer i-1's EPI-6 MoE2
            gemm_p<0><<<dim3(3, NTOK/128), 256, GEMM_SMEM>>>(phh, phl, EMBD, wqh, wql, bqkv_i,
                                                  pqkv, 3*EMBD, nullptr, nullptr,
                                                  nullptr, 0, EMBD,
                                                  nullptr, nullptr, nullptr, nullptr);
            int qt0 = (i == NLAYER-1) ? 12 : 0;
            attn_mma<<<BATCH*NHEAD, 256, ATTN_SMEM>>>(pqkv, poh, pol, qt0);
        }

        if (i < NLAYER-1) {
            // Wo + residual + LN2 + gate (fused)
            gemm_p<5><<<dim3(1, NTOK/128), 256, GEMM_SMEM>>>(poh, pol, EMBD, woh, wol, bo_i,
                                                  px, EMBD, phh, phl,
                                                  pgate, NEXP, EMBD,
                                                  ln2_w + i*EMBD, ln2_b + i*EMBD,
                                                  wg_i, bg_i);
            gemm_p<1><<<dim3(10, NTOK/128), 256, GEMM_SMEM>>>(phh, phl, EMBD, w1h, w1l, b1_i,
                                                   nullptr, NEXP*FFD, phidh, phidl,
                                                   pgate, NEXP, EMBD,
                                                   nullptr, nullptr, nullptr, nullptr);
            // MoE2 + residual + next layer's LN1 (fused)
            gemm_p<6><<<dim3(1, NTOK/128), 256, GEMM_SMEM>>>(phidh, phidl, NEXP*FFD, w2h, w2l, b2_i,
                                                  px, EMBD, phh, phl,
                                                  pgate, NEXP, NEXP*FFD,
                                                  ln1_w + (i+1)*EMBD, ln1_b + (i+1)*EMBD,
                                                  nullptr, nullptr);
        } else {
            const long rs = (long)SEQ*EMBD;
            gemm_p<3><<<dim3(1, BATCH/128), 256, GEMM_SMEM>>>(poh + (size_t)200*EMBD, pol + (size_t)200*EMBD, rs,
                                                   woh, wol, bo_i,
                                                   px + (size_t)200*EMBD, rs, nullptr, nullptr,
                                                   nullptr, 0, EMBD,
                                                   nullptr, nullptr, nullptr, nullptr);
            ln2g_p<<<BATCH/8, 256>>>(px, phh, phl, ln2_w + i*EMBD, ln2_b + i*EMBD,
                                     wg_i, bg_i, pgate, 200, SEQ);
            gemm_p<1><<<dim3(10, BATCH/128), 256, GEMM_SMEM>>>(phh + (size_t)200*EMBD, phl + (size_t)200*EMBD, rs,
                                                    w1h, w1l, b1_i,
                                                    nullptr, NEXP*FFD, phidh, phidl,
                                                    pgate + (size_t)200*NEXP, (long)SEQ*NEXP, EMBD,
                                                    nullptr, nullptr, nullptr, nullptr);
            gemm_p<4><<<dim3(1, BATCH/128), 256, GEMM_SMEM>>>(phidh, phidl, NEXP*FFD, w2h, w2l, b2_i,
                                                   px + (size_t)200*EMBD, rs, nullptr, nullptr,
                                                   pgate + (size_t)200*NEXP, (long)SEQ*NEXP,
                                                   NEXP*FFD,
                                                   nullptr, nullptr, nullptr, nullptr);
        }
    }

    copy_out_kernel<<<BATCH, 128>>>(px, out);
}